// round 2
// baseline (speedup 1.0000x reference)
#include <cuda_runtime.h>
#include <cstdint>

#define D   256
#define B   32
#define T   256
#define HW  4096

// Scratch (device globals — no allocations allowed)
__device__ float g_Q[(size_t)B * T * D];      // 8.4 MB
__device__ float g_K[(size_t)B * HW * D];     // 134 MB
__device__ float g_rmax[B * T];
__device__ float g_rsum[B * T];

// "is finite" threshold that survives fast-math folding of (x > -inf)
#define FIN_THRESH (-3.0e38f)

__device__ __forceinline__ float neg_inf() { return __int_as_float(0xff800000); }

// ---------------------------------------------------------------------------
// Projection: Y[r, j] = sum_k X[r,k] * W[j,k] + bias[j]
// Tile 128x128, 256 threads, 8x8 micro, k-chunk 16.
// Grid: (R/128, D/128)
// ---------------------------------------------------------------------------
__global__ __launch_bounds__(256) void proj_kernel(
    const float* __restrict__ X, const float* __restrict__ W,
    const float* __restrict__ bias, float* __restrict__ Y)
{
    __shared__ float As[16][128];
    __shared__ float Bs[16][128];

    const int tid  = threadIdx.x;
    const int tx   = tid & 15;    // 0..15  -> cols 8*tx
    const int ty   = tid >> 4;    // 0..15  -> rows 8*ty
    const int row0 = blockIdx.x * 128;
    const int col0 = blockIdx.y * 128;

    float acc[8][8];
    #pragma unroll
    for (int i = 0; i < 8; i++)
        #pragma unroll
        for (int j = 0; j < 8; j++) acc[i][j] = 0.f;

    const int lr = tid >> 2;  // 0..63
    const int lq = tid & 3;   // 0..3

    for (int kc = 0; kc < D; kc += 16) {
        #pragma unroll
        for (int h = 0; h < 2; h++) {
            int r = lr + 64 * h;
            float4 a = *(const float4*)(X + (size_t)(row0 + r) * D + kc + 4 * lq);
            As[4*lq+0][r] = a.x; As[4*lq+1][r] = a.y;
            As[4*lq+2][r] = a.z; As[4*lq+3][r] = a.w;
            float4 w = *(const float4*)(W + (size_t)(col0 + r) * D + kc + 4 * lq);
            Bs[4*lq+0][r] = w.x; Bs[4*lq+1][r] = w.y;
            Bs[4*lq+2][r] = w.z; Bs[4*lq+3][r] = w.w;
        }
        __syncthreads();
        #pragma unroll
        for (int k = 0; k < 16; k++) {
            float a[8], b[8];
            *(float4*)&a[0] = *(const float4*)&As[k][8 * ty];
            *(float4*)&a[4] = *(const float4*)&As[k][8 * ty + 4];
            *(float4*)&b[0] = *(const float4*)&Bs[k][8 * tx];
            *(float4*)&b[4] = *(const float4*)&Bs[k][8 * tx + 4];
            #pragma unroll
            for (int i = 0; i < 8; i++)
                #pragma unroll
                for (int j = 0; j < 8; j++)
                    acc[i][j] += a[i] * b[j];
        }
        __syncthreads();
    }

    #pragma unroll
    for (int i = 0; i < 8; i++) {
        const int row = row0 + 8 * ty + i;
        #pragma unroll
        for (int j = 0; j < 8; j += 4) {
            const int col = col0 + 8 * tx + j;
            float4 bb = *(const float4*)(bias + col);
            float4 o;
            o.x = acc[i][j+0] + bb.x;
            o.y = acc[i][j+1] + bb.y;
            o.z = acc[i][j+2] + bb.z;
            o.w = acc[i][j+3] + bb.w;
            *(float4*)(Y + (size_t)row * D + col) = o;
        }
    }
}

// ---------------------------------------------------------------------------
// Scores + online softmax stats.
// Block: batch b, 64 query rows. Tile 64 x 256 (s-dim), 256 threads, 8x8 micro.
// Writes raw logits (masked -> -inf) to out; tracks per-row (max, sumexp)
// entirely inside the block (each block owns complete rows).
// Grid: (B, T/64)
// ---------------------------------------------------------------------------
__global__ __launch_bounds__(256) void score_kernel(
    const int* __restrict__ Mmask, float* __restrict__ out)
{
    __shared__ float Qs[16][64];
    __shared__ float Ks[16][256];

    const int b   = blockIdx.x;
    const int t0  = blockIdx.y * 64;
    const int tid = threadIdx.x;
    const int tx  = tid & 31;   // col group: cols 8*tx  (0..255)
    const int ty  = tid >> 5;   // row group: rows 8*ty  (0..7) == warp id

    const float* __restrict__ Qb = g_Q + ((size_t)b * T + t0) * D;
    const float* __restrict__ Kb = g_K + (size_t)b * HW * D;
    const int*   __restrict__ Mb = Mmask + b * HW;

    const float NEGI = neg_inf();
    float rm[8], rs[8];
    #pragma unroll
    for (int i = 0; i < 8; i++) { rm[i] = NEGI; rs[i] = 0.f; }

    const int qr = tid >> 2;  // 0..63
    const int qq = tid & 3;   // 0..3

    for (int s0 = 0; s0 < HW; s0 += 256) {
        float acc[8][8];
        #pragma unroll
        for (int i = 0; i < 8; i++)
            #pragma unroll
            for (int j = 0; j < 8; j++) acc[i][j] = 0.f;

        for (int dc = 0; dc < D; dc += 16) {
            // Q tile: 64 rows x 16 d
            {
                float4 v = *(const float4*)(Qb + (size_t)qr * D + dc + 4 * qq);
                Qs[4*qq+0][qr] = v.x; Qs[4*qq+1][qr] = v.y;
                Qs[4*qq+2][qr] = v.z; Qs[4*qq+3][qr] = v.w;
            }
            // K tile: 256 cols x 16 d
            #pragma unroll
            for (int h = 0; h < 4; h++) {
                int idx = tid + 256 * h;
                int c   = idx >> 2;   // 0..255
                int q   = idx & 3;
                float4 v = *(const float4*)(Kb + (size_t)(s0 + c) * D + dc + 4 * q);
                Ks[4*q+0][c] = v.x; Ks[4*q+1][c] = v.y;
                Ks[4*q+2][c] = v.z; Ks[4*q+3][c] = v.w;
            }
            __syncthreads();
            #pragma unroll
            for (int k = 0; k < 16; k++) {
                float a[8], bb[8];
                *(float4*)&a[0]  = *(const float4*)&Qs[k][8 * ty];
                *(float4*)&a[4]  = *(const float4*)&Qs[k][8 * ty + 4];
                *(float4*)&bb[0] = *(const float4*)&Ks[k][8 * tx];
                *(float4*)&bb[4] = *(const float4*)&Ks[k][8 * tx + 4];
                #pragma unroll
                for (int i = 0; i < 8; i++)
                    #pragma unroll
                    for (int j = 0; j < 8; j++)
                        acc[i][j] += a[i] * bb[j];
            }
            __syncthreads();
        }

        // Epilogue: scale, mask, store logits, update online (max, sum)
        const float scale = 0.0625f;  // 1/sqrt(256)
        const int cbase = s0 + 8 * tx;
        int mk[8];
        #pragma unroll
        for (int j = 0; j < 8; j++) mk[j] = Mb[cbase + j];

        #pragma unroll
        for (int i = 0; i < 8; i++) {
            float z[8];
            #pragma unroll
            for (int j = 0; j < 8; j++)
                z[j] = (mk[j] != 0) ? acc[i][j] * scale : NEGI;

            const size_t orow = ((size_t)b * T + t0 + 8 * ty + i) * HW + cbase;
            *(float4*)(out + orow)     = make_float4(z[0], z[1], z[2], z[3]);
            *(float4*)(out + orow + 4) = make_float4(z[4], z[5], z[6], z[7]);

            // row max over this tile (full-warp: all 32 lanes share row i)
            float tmax = z[0];
            #pragma unroll
            for (int j = 1; j < 8; j++) tmax = fmaxf(tmax, z[j]);
            #pragma unroll
            for (int o = 16; o > 0; o >>= 1)
                tmax = fmaxf(tmax, __shfl_xor_sync(0xffffffffu, tmax, o));

            float mnew = fmaxf(rm[i], tmax);
            bool  live = (mnew >= FIN_THRESH);
            float tsum = 0.f;
            if (live) {
                #pragma unroll
                for (int j = 0; j < 8; j++) tsum += __expf(z[j] - mnew);  // -inf -> 0
            }
            #pragma unroll
            for (int o = 16; o > 0; o >>= 1)
                tsum += __shfl_xor_sync(0xffffffffu, tsum, o);

            float resc = live ? __expf(rm[i] - mnew) : 1.f;  // exp(-inf)=0 handles first tile
            rs[i] = rs[i] * resc + tsum;
            rm[i] = mnew;
        }
    }

    if (tx == 0) {
        #pragma unroll
        for (int i = 0; i < 8; i++) {
            const int gr = b * T + t0 + 8 * ty + i;
            g_rmax[gr] = rm[i];
            g_rsum[gr] = rs[i];
        }
    }
}

// ---------------------------------------------------------------------------
// Normalize in place: out = exp(z - max) / sum   (z = -inf -> 0)
// Grid: B*T blocks, 256 threads.
// ---------------------------------------------------------------------------
__global__ __launch_bounds__(256) void norm_kernel(float* __restrict__ out)
{
    const int row = blockIdx.x;
    const float m = g_rmax[row];
    const float s = g_rsum[row];
    float4* p = reinterpret_cast<float4*>(out + (size_t)row * HW);

    if (m >= FIN_THRESH && s > 0.f) {
        const float rinv = 1.f / s;
        for (int i = threadIdx.x; i < HW / 4; i += 256) {
            float4 v = p[i];
            v.x = __expf(v.x - m) * rinv;
            v.y = __expf(v.y - m) * rinv;
            v.z = __expf(v.z - m) * rinv;
            v.w = __expf(v.w - m) * rinv;
            p[i] = v;
        }
    } else {
        for (int i = threadIdx.x; i < HW / 4; i += 256)
            p[i] = make_float4(0.f, 0.f, 0.f, 0.f);
    }
}

// ---------------------------------------------------------------------------
extern "C" void kernel_launch(void* const* d_in, const int* in_sizes, int n_in,
                              void* d_out, int out_size)
{
    const float* F_a = (const float*)d_in[0];
    const float* F_s = (const float*)d_in[1];
    const int*   M_s = (const int*)  d_in[2];
    const float* Wq  = (const float*)d_in[3];
    const float* bq  = (const float*)d_in[4];
    const float* Wk  = (const float*)d_in[5];
    const float* bk  = (const float*)d_in[6];
    float* out = (float*)d_out;

    static float* qbuf = nullptr;
    static float* kbuf = nullptr;
    if (!qbuf) {
        cudaGetSymbolAddress((void**)&qbuf, g_Q);
        cudaGetSymbolAddress((void**)&kbuf, g_K);
    }

    proj_kernel<<<dim3((B * T)  / 128, D / 128), 256>>>(F_a, Wq, bq, qbuf);
    proj_kernel<<<dim3((B * HW) / 128, D / 128), 256>>>(F_s, Wk, bk, kbuf);
    score_kernel<<<dim3(B, T / 64), 256>>>(M_s, out);
    norm_kernel<<<B * T, 256>>>(out);
}

// round 3
// speedup vs baseline: 1.6575x; 1.6575x over previous
#include <cuda_runtime.h>
#include <cstdint>

#define D      256
#define B      32
#define T      256
#define HW     4096
#define SPLIT  4
#define SCHUNK (HW / SPLIT)   // 1024

// Scratch (device globals — allocations are forbidden)
__device__ float g_Q [(size_t)B * T * D];   // 8.4 MB : Q  = F_a @ Wq^T + bq
__device__ float g_Qt[(size_t)B * T * D];   // 8.4 MB : Qt = Q @ Wk
__device__ float g_cs[B * T];               // (Q . bk) * scale
__device__ float g_pm[B * T * SPLIT];       // partial row max
__device__ float g_ps[B * T * SPLIT];       // partial row sumexp

#define FIN_THRESH (-3.0e38f)
__device__ __forceinline__ float neg_inf() { return __int_as_float(0xff800000); }

// ---------------------------------------------------------------------------
// Y[r,j] = sum_k X[r,k] * W[j,k] + bias[j]   (torch Linear). 128x128 tile.
// ---------------------------------------------------------------------------
__global__ __launch_bounds__(256) void proj_kernel(
    const float* __restrict__ X, const float* __restrict__ W,
    const float* __restrict__ bias, float* __restrict__ Y)
{
    __shared__ float As[16][128];
    __shared__ float Bs[16][128];

    const int tid  = threadIdx.x;
    const int tx   = tid & 15;
    const int ty   = tid >> 4;
    const int row0 = blockIdx.x * 128;
    const int col0 = blockIdx.y * 128;

    float acc[8][8];
    #pragma unroll
    for (int i = 0; i < 8; i++)
        #pragma unroll
        for (int j = 0; j < 8; j++) acc[i][j] = 0.f;

    const int lr = tid >> 2;
    const int lq = tid & 3;

    for (int kc = 0; kc < D; kc += 16) {
        #pragma unroll
        for (int h = 0; h < 2; h++) {
            int r = lr + 64 * h;
            float4 a = *(const float4*)(X + (size_t)(row0 + r) * D + kc + 4 * lq);
            As[4*lq+0][r] = a.x; As[4*lq+1][r] = a.y;
            As[4*lq+2][r] = a.z; As[4*lq+3][r] = a.w;
            float4 w = *(const float4*)(W + (size_t)(col0 + r) * D + kc + 4 * lq);
            Bs[4*lq+0][r] = w.x; Bs[4*lq+1][r] = w.y;
            Bs[4*lq+2][r] = w.z; Bs[4*lq+3][r] = w.w;
        }
        __syncthreads();
        #pragma unroll
        for (int k = 0; k < 16; k++) {
            float a[8], b[8];
            *(float4*)&a[0] = *(const float4*)&As[k][8 * ty];
            *(float4*)&a[4] = *(const float4*)&As[k][8 * ty + 4];
            *(float4*)&b[0] = *(const float4*)&Bs[k][8 * tx];
            *(float4*)&b[4] = *(const float4*)&Bs[k][8 * tx + 4];
            #pragma unroll
            for (int i = 0; i < 8; i++)
                #pragma unroll
                for (int j = 0; j < 8; j++)
                    acc[i][j] += a[i] * b[j];
        }
        __syncthreads();
    }

    #pragma unroll
    for (int i = 0; i < 8; i++) {
        const int row = row0 + 8 * ty + i;
        #pragma unroll
        for (int j = 0; j < 8; j += 4) {
            const int col = col0 + 8 * tx + j;
            float4 bb = *(const float4*)(bias + col);
            float4 o;
            o.x = acc[i][j+0] + bb.x;
            o.y = acc[i][j+1] + bb.y;
            o.z = acc[i][j+2] + bb.z;
            o.w = acc[i][j+3] + bb.w;
            *(float4*)(Y + (size_t)row * D + col) = o;
        }
    }
}

// ---------------------------------------------------------------------------
// Y[r,j] = sum_k X[r,k] * W[k,j]   (non-transposed W, no bias). 128x128 tile.
// ---------------------------------------------------------------------------
__global__ __launch_bounds__(256) void proj_nt_kernel(
    const float* __restrict__ X, const float* __restrict__ W,
    float* __restrict__ Y)
{
    __shared__ float As[16][128];
    __shared__ float Bs[16][128];

    const int tid  = threadIdx.x;
    const int tx   = tid & 15;
    const int ty   = tid >> 4;
    const int row0 = blockIdx.x * 128;
    const int col0 = blockIdx.y * 128;

    float acc[8][8];
    #pragma unroll
    for (int i = 0; i < 8; i++)
        #pragma unroll
        for (int j = 0; j < 8; j++) acc[i][j] = 0.f;

    const int lr = tid >> 2;
    const int lq = tid & 3;

    for (int kc = 0; kc < D; kc += 16) {
        #pragma unroll
        for (int h = 0; h < 2; h++) {
            int r = lr + 64 * h;
            float4 a = *(const float4*)(X + (size_t)(row0 + r) * D + kc + 4 * lq);
            As[4*lq+0][r] = a.x; As[4*lq+1][r] = a.y;
            As[4*lq+2][r] = a.z; As[4*lq+3][r] = a.w;
        }
        // Bs[kk][c] = W[(kc+kk)*D + col0 + c]
        #pragma unroll
        for (int h = 0; h < 2; h++) {
            int idx = tid + 256 * h;
            int kk  = idx >> 5;       // 0..15
            int cq  = idx & 31;       // 0..31
            float4 w = *(const float4*)(W + (size_t)(kc + kk) * D + col0 + 4 * cq);
            *(float4*)&Bs[kk][4 * cq] = w;
        }
        __syncthreads();
        #pragma unroll
        for (int k = 0; k < 16; k++) {
            float a[8], b[8];
            *(float4*)&a[0] = *(const float4*)&As[k][8 * ty];
            *(float4*)&a[4] = *(const float4*)&As[k][8 * ty + 4];
            *(float4*)&b[0] = *(const float4*)&Bs[k][8 * tx];
            *(float4*)&b[4] = *(const float4*)&Bs[k][8 * tx + 4];
            #pragma unroll
            for (int i = 0; i < 8; i++)
                #pragma unroll
                for (int j = 0; j < 8; j++)
                    acc[i][j] += a[i] * b[j];
        }
        __syncthreads();
    }

    #pragma unroll
    for (int i = 0; i < 8; i++) {
        const int row = row0 + 8 * ty + i;
        #pragma unroll
        for (int j = 0; j < 8; j += 4) {
            const int col = col0 + 8 * tx + j;
            *(float4*)(Y + (size_t)row * D + col) =
                make_float4(acc[i][j+0], acc[i][j+1], acc[i][j+2], acc[i][j+3]);
        }
    }
}

// ---------------------------------------------------------------------------
// cs[t] = (Q[t,:] . bk) * scale.  One warp per row.
// ---------------------------------------------------------------------------
__global__ __launch_bounds__(256) void qc_kernel(const float* __restrict__ bk)
{
    const int row  = (blockIdx.x * blockDim.x + threadIdx.x) >> 5;
    const int lane = threadIdx.x & 31;
    if (row >= B * T) return;
    const float* q = g_Q + (size_t)row * D;
    float s = 0.f;
    #pragma unroll
    for (int i = 0; i < 8; i++) s += q[lane + 32 * i] * bk[lane + 32 * i];
    #pragma unroll
    for (int o = 16; o > 0; o >>= 1) s += __shfl_xor_sync(0xffffffffu, s, o);
    if (lane == 0) g_cs[row] = s * 0.0625f;
}

// ---------------------------------------------------------------------------
// Scores: z[t,s] = (Qt[t,:] . F_s[s,:]) * scale + cs[t], masked -> -inf.
// Block = (batch, 64-row tile, s-split). Each block covers 64 x 1024 logits,
// writing raw logits + partial (max, sumexp) for its split.
// Grid: (B, T/64, SPLIT), 256 threads, 8x8 micro.
// ---------------------------------------------------------------------------
__global__ __launch_bounds__(256) void score_kernel(
    const float* __restrict__ Fs, const int* __restrict__ Mmask,
    float* __restrict__ out)
{
    __shared__ float Qs[16][64];
    __shared__ float Ks[16][256];

    const int b   = blockIdx.x;
    const int t0  = blockIdx.y * 64;
    const int sp  = blockIdx.z;
    const int tid = threadIdx.x;
    const int tx  = tid & 31;   // cols 8*tx
    const int ty  = tid >> 5;   // rows 8*ty (warp id)

    const float* __restrict__ Qb = g_Qt + ((size_t)b * T + t0) * D;
    const float* __restrict__ Kb = Fs + (size_t)b * HW * D;
    const int*   __restrict__ Mb = Mmask + b * HW;

    const float NEGI = neg_inf();
    float rm[8], rs[8], csr[8];
    #pragma unroll
    for (int i = 0; i < 8; i++) {
        rm[i] = NEGI; rs[i] = 0.f;
        csr[i] = g_cs[b * T + t0 + 8 * ty + i];
    }

    const int qr = tid >> 2;
    const int qq = tid & 3;

    const int send = sp * SCHUNK + SCHUNK;
    for (int s0 = sp * SCHUNK; s0 < send; s0 += 256) {
        float acc[8][8];
        #pragma unroll
        for (int i = 0; i < 8; i++)
            #pragma unroll
            for (int j = 0; j < 8; j++) acc[i][j] = 0.f;

        for (int dc = 0; dc < D; dc += 16) {
            {
                float4 v = *(const float4*)(Qb + (size_t)qr * D + dc + 4 * qq);
                Qs[4*qq+0][qr] = v.x; Qs[4*qq+1][qr] = v.y;
                Qs[4*qq+2][qr] = v.z; Qs[4*qq+3][qr] = v.w;
            }
            #pragma unroll
            for (int h = 0; h < 4; h++) {
                int idx = tid + 256 * h;
                int c   = idx >> 2;
                int q   = idx & 3;
                float4 v = *(const float4*)(Kb + (size_t)(s0 + c) * D + dc + 4 * q);
                Ks[4*q+0][c] = v.x; Ks[4*q+1][c] = v.y;
                Ks[4*q+2][c] = v.z; Ks[4*q+3][c] = v.w;
            }
            __syncthreads();
            #pragma unroll
            for (int k = 0; k < 16; k++) {
                float a[8], bb[8];
                *(float4*)&a[0]  = *(const float4*)&Qs[k][8 * ty];
                *(float4*)&a[4]  = *(const float4*)&Qs[k][8 * ty + 4];
                *(float4*)&bb[0] = *(const float4*)&Ks[k][8 * tx];
                *(float4*)&bb[4] = *(const float4*)&Ks[k][8 * tx + 4];
                #pragma unroll
                for (int i = 0; i < 8; i++)
                    #pragma unroll
                    for (int j = 0; j < 8; j++)
                        acc[i][j] += a[i] * bb[j];
            }
            __syncthreads();
        }

        const float scale = 0.0625f;  // 1/sqrt(256)
        const int cbase = s0 + 8 * tx;
        int mk[8];
        #pragma unroll
        for (int j = 0; j < 8; j++) mk[j] = Mb[cbase + j];

        #pragma unroll
        for (int i = 0; i < 8; i++) {
            float z[8];
            #pragma unroll
            for (int j = 0; j < 8; j++)
                z[j] = (mk[j] != 0) ? acc[i][j] * scale + csr[i] : NEGI;

            const size_t orow = ((size_t)b * T + t0 + 8 * ty + i) * HW + cbase;
            *(float4*)(out + orow)     = make_float4(z[0], z[1], z[2], z[3]);
            *(float4*)(out + orow + 4) = make_float4(z[4], z[5], z[6], z[7]);

            float tmax = z[0];
            #pragma unroll
            for (int j = 1; j < 8; j++) tmax = fmaxf(tmax, z[j]);
            #pragma unroll
            for (int o = 16; o > 0; o >>= 1)
                tmax = fmaxf(tmax, __shfl_xor_sync(0xffffffffu, tmax, o));

            float mnew = fmaxf(rm[i], tmax);
            bool  live = (mnew >= FIN_THRESH);
            float tsum = 0.f;
            if (live) {
                #pragma unroll
                for (int j = 0; j < 8; j++) tsum += __expf(z[j] - mnew);
            }
            #pragma unroll
            for (int o = 16; o > 0; o >>= 1)
                tsum += __shfl_xor_sync(0xffffffffu, tsum, o);

            float resc = live ? __expf(rm[i] - mnew) : 1.f;
            rs[i] = rs[i] * resc + tsum;
            rm[i] = mnew;
        }
    }

    if (tx == 0) {
        #pragma unroll
        for (int i = 0; i < 8; i++) {
            const int gr = b * T + t0 + 8 * ty + i;
            g_pm[gr * SPLIT + sp] = rm[i];
            g_ps[gr * SPLIT + sp] = rs[i];
        }
    }
}

// ---------------------------------------------------------------------------
// Merge partial stats + normalize in place. Grid: B*T blocks.
// ---------------------------------------------------------------------------
__global__ __launch_bounds__(256) void norm_kernel(float* __restrict__ out)
{
    const int row = blockIdx.x;

    float m = neg_inf();
    #pragma unroll
    for (int i = 0; i < SPLIT; i++) m = fmaxf(m, g_pm[row * SPLIT + i]);

    float4* p = reinterpret_cast<float4*>(out + (size_t)row * HW);

    if (m >= FIN_THRESH) {
        float s = 0.f;
        #pragma unroll
        for (int i = 0; i < SPLIT; i++) {
            float pmv = g_pm[row * SPLIT + i];
            float w   = (pmv >= FIN_THRESH) ? __expf(pmv - m) : 0.f;
            s += g_ps[row * SPLIT + i] * w;
        }
        const float rinv = 1.f / s;
        for (int i = threadIdx.x; i < HW / 4; i += 256) {
            float4 v = p[i];
            v.x = __expf(v.x - m) * rinv;
            v.y = __expf(v.y - m) * rinv;
            v.z = __expf(v.z - m) * rinv;
            v.w = __expf(v.w - m) * rinv;
            p[i] = v;
        }
    } else {
        for (int i = threadIdx.x; i < HW / 4; i += 256)
            p[i] = make_float4(0.f, 0.f, 0.f, 0.f);
    }
}

// ---------------------------------------------------------------------------
extern "C" void kernel_launch(void* const* d_in, const int* in_sizes, int n_in,
                              void* d_out, int out_size)
{
    const float* F_a = (const float*)d_in[0];
    const float* F_s = (const float*)d_in[1];
    const int*   M_s = (const int*)  d_in[2];
    const float* Wq  = (const float*)d_in[3];
    const float* bq  = (const float*)d_in[4];
    const float* Wk  = (const float*)d_in[5];
    const float* bk  = (const float*)d_in[6];
    float* out = (float*)d_out;

    static float* qbuf  = nullptr;
    static float* qtbuf = nullptr;
    if (!qbuf) {
        cudaGetSymbolAddress((void**)&qbuf,  g_Q);
        cudaGetSymbolAddress((void**)&qtbuf, g_Qt);
    }

    // Q = F_a @ Wq^T + bq
    proj_kernel<<<dim3((B * T) / 128, D / 128), 256>>>(F_a, Wq, bq, qbuf);
    // Qt = Q @ Wk
    proj_nt_kernel<<<dim3((B * T) / 128, D / 128), 256>>>(qbuf, Wk, qtbuf);
    // cs = (Q . bk) * scale
    qc_kernel<<<(B * T * 32) / 256, 256>>>(bk);
    // logits + partial softmax stats
    score_kernel<<<dim3(B, T / 64, SPLIT), 256>>>(F_s, M_s, out);
    // merge + normalize
    norm_kernel<<<B * T, 256>>>(out);
}

// round 8
// speedup vs baseline: 3.4981x; 2.1105x over previous
#include <cuda_runtime.h>
#include <cuda_bf16.h>
#include <cstdint>

#define D      256
#define B      32
#define T      256
#define HW     4096
#define SPLIT  64            // per-row stat chunks of 64 s-columns

// ---------------------------------------------------------------------------
// Device-global scratch (allocations forbidden)
// ---------------------------------------------------------------------------
__device__ float          g_Q [(size_t)B * T * D];     // Q = F_a@Wq^T + bq (fp32)
__device__ __nv_bfloat16  g_Qh[(size_t)B * T * D];     // hi(Qt*scale)
__device__ __nv_bfloat16  g_Ql[(size_t)B * T * D];     // lo(Qt*scale)
__device__ __nv_bfloat16  g_Fh[(size_t)B * HW * D];    // hi(F_s)
__device__ __nv_bfloat16  g_Fl[(size_t)B * HW * D];    // lo(F_s)
__device__ float          g_cs[B * T];                 // (Q.bk)*scale
__device__ float          g_pm[(size_t)B * T * SPLIT]; // partial row max
__device__ float          g_ps[(size_t)B * T * SPLIT]; // partial row sumexp

#define FIN_THRESH (-3.0e38f)
__device__ __forceinline__ float neg_inf() { return __int_as_float(0xff800000); }

__device__ __forceinline__ uint32_t smem_to_u32(const void* p) {
    uint32_t a;
    asm("{ .reg .u64 t; cvta.to.shared.u64 t, %1; cvt.u32.u64 %0, t; }"
        : "=r"(a) : "l"(p));
    return a;
}

// ldmatrix x4 (no trans), b16
__device__ __forceinline__ void ldsm_x4(uint32_t* r, uint32_t addr) {
    asm volatile("ldmatrix.sync.aligned.m8n8.x4.shared.b16 {%0,%1,%2,%3}, [%4];"
                 : "=r"(r[0]), "=r"(r[1]), "=r"(r[2]), "=r"(r[3]) : "r"(addr));
}

// mma m16n8k16 row.col f32.bf16.bf16.f32
__device__ __forceinline__ void mma_bf16(float* c, const uint32_t* a,
                                         uint32_t b0, uint32_t b1) {
    asm volatile(
        "mma.sync.aligned.m16n8k16.row.col.f32.bf16.bf16.f32 "
        "{%0,%1,%2,%3}, {%4,%5,%6,%7}, {%8,%9}, {%0,%1,%2,%3};"
        : "+f"(c[0]), "+f"(c[1]), "+f"(c[2]), "+f"(c[3])
        : "r"(a[0]), "r"(a[1]), "r"(a[2]), "r"(a[3]), "r"(b0), "r"(b1));
}

// fp32 -> bf16 hi/lo split
__device__ __forceinline__ void split_bf16(float x, __nv_bfloat16& h, __nv_bfloat16& l) {
    h = __float2bfloat16_rn(x);
    l = __float2bfloat16_rn(x - __bfloat162float(h));
}

// ---------------------------------------------------------------------------
// Q projection: Y = F_a @ Wq^T + bq  (fp32, 128x128 tile)
// ---------------------------------------------------------------------------
__global__ __launch_bounds__(256) void proj_kernel(
    const float* __restrict__ X, const float* __restrict__ W,
    const float* __restrict__ bias, float* __restrict__ Y)
{
    __shared__ float As[16][128];
    __shared__ float Bs[16][128];

    const int tid  = threadIdx.x;
    const int tx   = tid & 15;
    const int ty   = tid >> 4;
    const int row0 = blockIdx.x * 128;
    const int col0 = blockIdx.y * 128;

    float acc[8][8];
    #pragma unroll
    for (int i = 0; i < 8; i++)
        #pragma unroll
        for (int j = 0; j < 8; j++) acc[i][j] = 0.f;

    const int lr = tid >> 2;
    const int lq = tid & 3;

    for (int kc = 0; kc < D; kc += 16) {
        #pragma unroll
        for (int h = 0; h < 2; h++) {
            int r = lr + 64 * h;
            float4 a = *(const float4*)(X + (size_t)(row0 + r) * D + kc + 4 * lq);
            As[4*lq+0][r] = a.x; As[4*lq+1][r] = a.y;
            As[4*lq+2][r] = a.z; As[4*lq+3][r] = a.w;
            float4 w = *(const float4*)(W + (size_t)(col0 + r) * D + kc + 4 * lq);
            Bs[4*lq+0][r] = w.x; Bs[4*lq+1][r] = w.y;
            Bs[4*lq+2][r] = w.z; Bs[4*lq+3][r] = w.w;
        }
        __syncthreads();
        #pragma unroll
        for (int k = 0; k < 16; k++) {
            float a[8], b[8];
            *(float4*)&a[0] = *(const float4*)&As[k][8 * ty];
            *(float4*)&a[4] = *(const float4*)&As[k][8 * ty + 4];
            *(float4*)&b[0] = *(const float4*)&Bs[k][8 * tx];
            *(float4*)&b[4] = *(const float4*)&Bs[k][8 * tx + 4];
            #pragma unroll
            for (int i = 0; i < 8; i++)
                #pragma unroll
                for (int j = 0; j < 8; j++)
                    acc[i][j] += a[i] * b[j];
        }
        __syncthreads();
    }

    #pragma unroll
    for (int i = 0; i < 8; i++) {
        const int row = row0 + 8 * ty + i;
        #pragma unroll
        for (int j = 0; j < 8; j += 4) {
            const int col = col0 + 8 * tx + j;
            float4 bb = *(const float4*)(bias + col);
            float4 o;
            o.x = acc[i][j+0] + bb.x;
            o.y = acc[i][j+1] + bb.y;
            o.z = acc[i][j+2] + bb.z;
            o.w = acc[i][j+3] + bb.w;
            *(float4*)(Y + (size_t)row * D + col) = o;
        }
    }
}

// ---------------------------------------------------------------------------
// Qt = (Q @ Wk) * scale, written as bf16 hi/lo split. 128x128 tile.
// ---------------------------------------------------------------------------
__global__ __launch_bounds__(256) void proj_nt_split_kernel(
    const float* __restrict__ X, const float* __restrict__ W)
{
    __shared__ float As[16][128];
    __shared__ float Bs[16][128];

    const int tid  = threadIdx.x;
    const int tx   = tid & 15;
    const int ty   = tid >> 4;
    const int row0 = blockIdx.x * 128;
    const int col0 = blockIdx.y * 128;

    float acc[8][8];
    #pragma unroll
    for (int i = 0; i < 8; i++)
        #pragma unroll
        for (int j = 0; j < 8; j++) acc[i][j] = 0.f;

    const int lr = tid >> 2;
    const int lq = tid & 3;

    for (int kc = 0; kc < D; kc += 16) {
        #pragma unroll
        for (int h = 0; h < 2; h++) {
            int r = lr + 64 * h;
            float4 a = *(const float4*)(X + (size_t)(row0 + r) * D + kc + 4 * lq);
            As[4*lq+0][r] = a.x; As[4*lq+1][r] = a.y;
            As[4*lq+2][r] = a.z; As[4*lq+3][r] = a.w;
        }
        #pragma unroll
        for (int h = 0; h < 2; h++) {
            int idx = tid + 256 * h;
            int kk  = idx >> 5;
            int cq  = idx & 31;
            float4 w = *(const float4*)(W + (size_t)(kc + kk) * D + col0 + 4 * cq);
            *(float4*)&Bs[kk][4 * cq] = w;
        }
        __syncthreads();
        #pragma unroll
        for (int k = 0; k < 16; k++) {
            float a[8], b[8];
            *(float4*)&a[0] = *(const float4*)&As[k][8 * ty];
            *(float4*)&a[4] = *(const float4*)&As[k][8 * ty + 4];
            *(float4*)&b[0] = *(const float4*)&Bs[k][8 * tx];
            *(float4*)&b[4] = *(const float4*)&Bs[k][8 * tx + 4];
            #pragma unroll
            for (int i = 0; i < 8; i++)
                #pragma unroll
                for (int j = 0; j < 8; j++)
                    acc[i][j] += a[i] * b[j];
        }
        __syncthreads();
    }

    const float scale = 0.0625f;  // 1/sqrt(256)
    #pragma unroll
    for (int i = 0; i < 8; i++) {
        const size_t row = row0 + 8 * ty + i;
        #pragma unroll
        for (int j = 0; j < 8; j++) {
            const int col = col0 + 8 * tx + j;
            __nv_bfloat16 h, l;
            split_bf16(acc[i][j] * scale, h, l);
            g_Qh[row * D + col] = h;
            g_Ql[row * D + col] = l;
        }
    }
}

// ---------------------------------------------------------------------------
// F_s fp32 -> bf16 hi/lo. 8 elements/thread, vectorized.
// ---------------------------------------------------------------------------
__global__ __launch_bounds__(256) void conv_fs_kernel(const float* __restrict__ Fs)
{
    const size_t i = ((size_t)blockIdx.x * 256 + threadIdx.x) * 8;
    float4 v0 = *(const float4*)(Fs + i);
    float4 v1 = *(const float4*)(Fs + i + 4);
    float x[8] = {v0.x, v0.y, v0.z, v0.w, v1.x, v1.y, v1.z, v1.w};
    __nv_bfloat16 h[8], l[8];
    #pragma unroll
    for (int k = 0; k < 8; k++) split_bf16(x[k], h[k], l[k]);
    uint4 ph, pl;
    ph.x = ((uint32_t)__bfloat16_as_ushort(h[1]) << 16) | __bfloat16_as_ushort(h[0]);
    ph.y = ((uint32_t)__bfloat16_as_ushort(h[3]) << 16) | __bfloat16_as_ushort(h[2]);
    ph.z = ((uint32_t)__bfloat16_as_ushort(h[5]) << 16) | __bfloat16_as_ushort(h[4]);
    ph.w = ((uint32_t)__bfloat16_as_ushort(h[7]) << 16) | __bfloat16_as_ushort(h[6]);
    pl.x = ((uint32_t)__bfloat16_as_ushort(l[1]) << 16) | __bfloat16_as_ushort(l[0]);
    pl.y = ((uint32_t)__bfloat16_as_ushort(l[3]) << 16) | __bfloat16_as_ushort(l[2]);
    pl.z = ((uint32_t)__bfloat16_as_ushort(l[5]) << 16) | __bfloat16_as_ushort(l[4]);
    pl.w = ((uint32_t)__bfloat16_as_ushort(l[7]) << 16) | __bfloat16_as_ushort(l[6]);
    *(uint4*)(g_Fh + i) = ph;
    *(uint4*)(g_Fl + i) = pl;
}

// ---------------------------------------------------------------------------
// cs[t] = (Q[t,:] . bk) * scale. One warp per row.
// ---------------------------------------------------------------------------
__global__ __launch_bounds__(256) void qc_kernel(const float* __restrict__ bk)
{
    const int row  = (blockIdx.x * blockDim.x + threadIdx.x) >> 5;
    const int lane = threadIdx.x & 31;
    if (row >= B * T) return;
    const float* q = g_Q + (size_t)row * D;
    float s = 0.f;
    #pragma unroll
    for (int i = 0; i < 8; i++) s += q[lane + 32 * i] * bk[lane + 32 * i];
    #pragma unroll
    for (int o = 16; o > 0; o >>= 1) s += __shfl_xor_sync(0xffffffffu, s, o);
    if (lane == 0) g_cs[row] = s * 0.0625f;
}

// ---------------------------------------------------------------------------
// mma.sync score kernel.
// CTA tile 128(M) x 128(N), K=256 streamed in 4 chunks of 64.
// 8 warps (4 m-tiles x 2 n-halves), warp tile 32x64.
// 3 bf16 terms: Ah*Bh + Al*Bh + Ah*Bl (lo*lo dropped, ~2^-16 rel).
// Grid (B, T/128, HW/128) = (32, 2, 32), 256 threads.
// ---------------------------------------------------------------------------
#define SM_AH   0
#define SM_AL   16384
#define SM_BH   32768
#define SM_BL   49152
#define SM_MASK 65536
#define SM_TOT  66048

// load 128 rows x 64 bf16 cols (global row stride D) into XOR-swizzled smem:
// smem_off(r, chunk) = r*128 + ((chunk ^ (r&7)) << 4), chunk = 16B unit (8 bf16)
__device__ __forceinline__ void ld_tile64(uint8_t* dst,
                                          const __nv_bfloat16* __restrict__ g,
                                          int kc, int tid)
{
    #pragma unroll
    for (int i = 0; i < 4; i++) {
        const int v = tid + 256 * i;       // 0..1023
        const int r = v >> 3;              // 0..127
        const int c = v & 7;               // chunk 0..7
        const uint32_t off = (uint32_t)r * 128u + (uint32_t)((c ^ (r & 7)) << 4);
        *(uint4*)(dst + off) = *(const uint4*)(g + (size_t)r * D + kc + c * 8);
    }
}

__global__ __launch_bounds__(256, 2)
void score_mma_kernel(const int* __restrict__ Mmask, float* __restrict__ out)
{
    extern __shared__ __align__(128) uint8_t smem[];
    const int b    = blockIdx.x;
    const int t0   = blockIdx.y * 128;
    const int sp   = blockIdx.z;
    const int s0   = sp * 128;
    const int tid  = threadIdx.x;
    const int wid  = tid >> 5;
    const int lane = tid & 31;
    const int wm   = wid & 3;     // m-tile (32 rows)
    const int wn   = wid >> 2;    // n-half (64 cols)
    const uint32_t sb = smem_to_u32(smem);

    const __nv_bfloat16* __restrict__ Ah = g_Qh + (size_t)(b * T + t0) * D;
    const __nv_bfloat16* __restrict__ Al = g_Ql + (size_t)(b * T + t0) * D;
    const __nv_bfloat16* __restrict__ Bh = g_Fh + (size_t)(b * HW + s0) * D;
    const __nv_bfloat16* __restrict__ Bl = g_Fl + (size_t)(b * HW + s0) * D;

    if (tid < 128) ((int*)(smem + SM_MASK))[tid] = Mmask[b * HW + s0 + tid];

    // hoisted invariant fragment addresses (depend only on lane/warp, not kc/ks)
    const uint32_t rA    = (uint32_t)(wm * 32 + (lane & 15));          // A rows, mt=0
    const uint32_t chA   = (uint32_t)(lane >> 4);                      // k-half select
    const uint32_t nB    = (uint32_t)(wn * 64 + (lane & 7) + ((lane >> 4) << 3));
    const uint32_t chB   = (uint32_t)((lane >> 3) & 1);

    float acc[2][8][4];
    #pragma unroll
    for (int mt = 0; mt < 2; mt++)
        #pragma unroll
        for (int nt = 0; nt < 8; nt++)
            #pragma unroll
            for (int q = 0; q < 4; q++) acc[mt][nt][q] = 0.f;

    #pragma unroll 1
    for (int kc = 0; kc < D; kc += 64) {
        __syncthreads();
        ld_tile64(smem + SM_AH, Ah, kc, tid);
        ld_tile64(smem + SM_AL, Al, kc, tid);
        ld_tile64(smem + SM_BH, Bh, kc, tid);
        ld_tile64(smem + SM_BL, Bl, kc, tid);
        __syncthreads();

        #pragma unroll
        for (int ks = 0; ks < 4; ks++) {
            // A fragments (hi & lo) for both 16-row sub-tiles
            uint32_t ah[2][4], al[2][4];
            #pragma unroll
            for (int mt = 0; mt < 2; mt++) {
                const uint32_t r   = rA + (uint32_t)(mt * 16);
                const uint32_t ch  = (uint32_t)(ks * 2) + chA;
                const uint32_t off = r * 128u + (((ch ^ (r & 7)) & 7u) << 4);
                ldsm_x4(ah[mt], sb + SM_AH + off);
                ldsm_x4(al[mt], sb + SM_AL + off);
            }
            // B fragments, 2 n8-tiles per ldmatrix.x4
            #pragma unroll
            for (int np = 0; np < 4; np++) {
                const uint32_t n   = nB + (uint32_t)(np * 16);
                const uint32_t ch  = (uint32_t)(ks * 2) + chB;
                const uint32_t off = n * 128u + (((ch ^ (n & 7)) & 7u) << 4);
                uint32_t bh[4], bl[4];
                ldsm_x4(bh, sb + SM_BH + off);
                ldsm_x4(bl, sb + SM_BL + off);
                #pragma unroll
                for (int mt = 0; mt < 2; mt++) {
                    mma_bf16(acc[mt][2*np+0], ah[mt], bh[0], bh[1]);
                    mma_bf16(acc[mt][2*np+1], ah[mt], bh[2], bh[3]);
                    mma_bf16(acc[mt][2*np+0], al[mt], bh[0], bh[1]);
                    mma_bf16(acc[mt][2*np+1], al[mt], bh[2], bh[3]);
                    mma_bf16(acc[mt][2*np+0], ah[mt], bl[0], bl[1]);
                    mma_bf16(acc[mt][2*np+1], ah[mt], bl[2], bl[3]);
                }
            }
        }
    }

    // ------------------------------------------------------------------
    // Epilogue: mask, +cs, write logits (float2), per-row max/sumexp
    // C frag: c0,c1 -> row qr, cols qc..qc+1; c2,c3 -> row qr+8.
    // ------------------------------------------------------------------
    const float NEGI = neg_inf();
    const int*  msk  = (const int*)(smem + SM_MASK);
    const int   qr   = lane >> 2;
    const int   qc   = (lane & 3) * 2;

    // mask regs for this thread's 16 columns
    int mk0[8], mk1[8];
    #pragma unroll
    for (int nt = 0; nt < 8; nt++) {
        mk0[nt] = msk[wn * 64 + nt * 8 + qc];
        mk1[nt] = msk[wn * 64 + nt * 8 + qc + 1];
    }

    #pragma unroll
    for (int mt = 0; mt < 2; mt++) {
        #pragma unroll
        for (int inst = 0; inst < 2; inst++) {   // c01 (row qr) / c23 (row qr+8)
            const int r    = wm * 32 + mt * 16 + inst * 8 + qr;
            const int grow = b * T + t0 + r;
            const float cs = g_cs[grow];

            float z[16];
            float rmax = NEGI;
            #pragma unroll
            for (int nt = 0; nt < 8; nt++) {
                const float v0 = acc[mt][nt][inst * 2 + 0] + cs;
                const float v1 = acc[mt][nt][inst * 2 + 1] + cs;
                z[2*nt+0] = (mk0[nt] != 0) ? v0 : NEGI;
                z[2*nt+1] = (mk1[nt] != 0) ? v1 : NEGI;
                rmax = fmaxf(rmax, fmaxf(z[2*nt+0], z[2*nt+1]));
            }
            // store logits: float2, 8 stores
            float* orow = out + (size_t)grow * HW + s0 + wn * 64 + qc;
            #pragma unroll
            for (int nt = 0; nt < 8; nt++)
                *(float2*)(orow + nt * 8) = make_float2(z[2*nt], z[2*nt+1]);

            // reduce across the quad (lanes differing in bits 0,1 share the row)
            rmax = fmaxf(rmax, __shfl_xor_sync(0xffffffffu, rmax, 1));
            rmax = fmaxf(rmax, __shfl_xor_sync(0xffffffffu, rmax, 2));

            float rsum = 0.f;
            if (rmax >= FIN_THRESH) {
                #pragma unroll
                for (int j = 0; j < 16; j++) rsum += __expf(z[j] - rmax);
            }
            rsum += __shfl_xor_sync(0xffffffffu, rsum, 1);
            rsum += __shfl_xor_sync(0xffffffffu, rsum, 2);

            if ((lane & 3) == 0) {
                const size_t si = (size_t)grow * SPLIT + sp * 2 + wn;
                g_pm[si] = rmax;
                g_ps[si] = rsum;
            }
        }
    }
}

// ---------------------------------------------------------------------------
// Merge 64 partial stats + normalize in place. Grid: B*T blocks.
// ---------------------------------------------------------------------------
__global__ __launch_bounds__(256) void norm_kernel(float* __restrict__ out)
{
    const int row = blockIdx.x;

    float m = neg_inf();
    for (int i = 0; i < SPLIT; i++) m = fmaxf(m, g_pm[(size_t)row * SPLIT + i]);

    float4* p = reinterpret_cast<float4*>(out + (size_t)row * HW);

    if (m >= FIN_THRESH) {
        float s = 0.f;
        for (int i = 0; i < SPLIT; i++) {
            const float pmv = g_pm[(size_t)row * SPLIT + i];
            const float w   = (pmv >= FIN_THRESH) ? __expf(pmv - m) : 0.f;
            s += g_ps[(size_t)row * SPLIT + i] * w;
        }
        const float rinv = 1.f / s;
        for (int i = threadIdx.x; i < HW / 4; i += 256) {
            float4 v = p[i];
            v.x = __expf(v.x - m) * rinv;
            v.y = __expf(v.y - m) * rinv;
            v.z = __expf(v.z - m) * rinv;
            v.w = __expf(v.w - m) * rinv;
            p[i] = v;
        }
    } else {
        for (int i = threadIdx.x; i < HW / 4; i += 256)
            p[i] = make_float4(0.f, 0.f, 0.f, 0.f);
    }
}

// ---------------------------------------------------------------------------
extern "C" void kernel_launch(void* const* d_in, const int* in_sizes, int n_in,
                              void* d_out, int out_size)
{
    const float* F_a = (const float*)d_in[0];
    const float* F_s = (const float*)d_in[1];
    const int*   M_s = (const int*)  d_in[2];
    const float* Wq  = (const float*)d_in[3];
    const float* bq  = (const float*)d_in[4];
    const float* Wk  = (const float*)d_in[5];
    const float* bk  = (const float*)d_in[6];
    float* out = (float*)d_out;

    static float* qbuf = nullptr;
    if (!qbuf) {
        cudaGetSymbolAddress((void**)&qbuf, g_Q);
        cudaFuncSetAttribute(score_mma_kernel,
                             cudaFuncAttributeMaxDynamicSharedMemorySize, SM_TOT);
    }

    // Q = F_a @ Wq^T + bq
    proj_kernel<<<dim3((B * T) / 128, D / 128), 256>>>(F_a, Wq, bq, qbuf);
    // Qt = (Q @ Wk) * scale -> bf16 hi/lo
    proj_nt_split_kernel<<<dim3((B * T) / 128, D / 128), 256>>>(qbuf, Wk);
    // cs = (Q . bk) * scale
    qc_kernel<<<(B * T * 32) / 256, 256>>>(bk);
    // F_s -> bf16 hi/lo
    conv_fs_kernel<<<(int)(((size_t)B * HW * D) / (256 * 8)), 256>>>(F_s);
    // logits + partial stats (HMMA)
    score_mma_kernel<<<dim3(B, T / 128, HW / 128), 256, SM_TOT>>>(M_s, out);
    // merge + normalize
    norm_kernel<<<B * T, 256>>>(out);
}

// round 11
// speedup vs baseline: 3.6319x; 1.0383x over previous
#include <cuda_runtime.h>
#include <cuda_bf16.h>
#include <cstdint>

#define D      256
#define B      32
#define T      256
#define HW     4096
#define SPLIT  64            // per-row stat chunks of 64 s-columns

// ---------------------------------------------------------------------------
// Device-global scratch (allocations forbidden)
// ---------------------------------------------------------------------------
__device__ float          g_Q [(size_t)B * T * D];     // Q = F_a@Wq^T + bq (fp32)
__device__ __nv_bfloat16  g_Qh[(size_t)B * T * D];     // hi(Qt*scale)
__device__ __nv_bfloat16  g_Ql[(size_t)B * T * D];     // lo(Qt*scale)
__device__ __nv_bfloat16  g_Fh[(size_t)B * HW * D];    // hi(F_s)
__device__ __nv_bfloat16  g_Fl[(size_t)B * HW * D];    // lo(F_s)
__device__ float          g_cs[B * T];                 // (Q.bk)*scale
__device__ float          g_pm[(size_t)B * T * SPLIT]; // partial row max
__device__ float          g_ps[(size_t)B * T * SPLIT]; // partial row sumexp

#define FIN_THRESH (-3.0e38f)
__device__ __forceinline__ float neg_inf() { return __int_as_float(0xff800000); }

__device__ __forceinline__ uint32_t smem_to_u32(const void* p) {
    uint32_t a;
    asm("{ .reg .u64 t; cvta.to.shared.u64 t, %1; cvt.u32.u64 %0, t; }"
        : "=r"(a) : "l"(p));
    return a;
}

// ldmatrix x4 (no trans), b16
__device__ __forceinline__ void ldsm_x4(uint32_t* r, uint32_t addr) {
    asm volatile("ldmatrix.sync.aligned.m8n8.x4.shared.b16 {%0,%1,%2,%3}, [%4];"
                 : "=r"(r[0]), "=r"(r[1]), "=r"(r[2]), "=r"(r[3]) : "r"(addr));
}

// mma m16n8k16 row.col f32.bf16.bf16.f32
__device__ __forceinline__ void mma_bf16(float* c, const uint32_t* a,
                                         uint32_t b0, uint32_t b1) {
    asm volatile(
        "mma.sync.aligned.m16n8k16.row.col.f32.bf16.bf16.f32 "
        "{%0,%1,%2,%3}, {%4,%5,%6,%7}, {%8,%9}, {%0,%1,%2,%3};"
        : "+f"(c[0]), "+f"(c[1]), "+f"(c[2]), "+f"(c[3])
        : "r"(a[0]), "r"(a[1]), "r"(a[2]), "r"(a[3]), "r"(b0), "r"(b1));
}

// cp.async 16B (bypass L1), commit/wait
#define CP_ASYNC16(smem, gptr) \
    asm volatile("cp.async.cg.shared.global [%0], [%1], 16;" \
                 :: "r"(smem), "l"(gptr) : "memory")
#define CP_COMMIT() asm volatile("cp.async.commit_group;" ::: "memory")
#define CP_WAIT(n)  asm volatile("cp.async.wait_group %0;" :: "n"(n) : "memory")

// fp32 -> bf16 hi/lo split
__device__ __forceinline__ void split_bf16(float x, __nv_bfloat16& h, __nv_bfloat16& l) {
    h = __float2bfloat16_rn(x);
    l = __float2bfloat16_rn(x - __bfloat162float(h));
}

// ---------------------------------------------------------------------------
// Q projection: Y = F_a @ Wq^T + bq  (fp32, 128x128 tile)
// ---------------------------------------------------------------------------
__global__ __launch_bounds__(256) void proj_kernel(
    const float* __restrict__ X, const float* __restrict__ W,
    const float* __restrict__ bias, float* __restrict__ Y)
{
    __shared__ float As[16][128];
    __shared__ float Bs[16][128];

    const int tid  = threadIdx.x;
    const int tx   = tid & 15;
    const int ty   = tid >> 4;
    const int row0 = blockIdx.x * 128;
    const int col0 = blockIdx.y * 128;

    float acc[8][8];
    #pragma unroll
    for (int i = 0; i < 8; i++)
        #pragma unroll
        for (int j = 0; j < 8; j++) acc[i][j] = 0.f;

    const int lr = tid >> 2;
    const int lq = tid & 3;

    for (int kc = 0; kc < D; kc += 16) {
        #pragma unroll
        for (int h = 0; h < 2; h++) {
            int r = lr + 64 * h;
            float4 a = *(const float4*)(X + (size_t)(row0 + r) * D + kc + 4 * lq);
            As[4*lq+0][r] = a.x; As[4*lq+1][r] = a.y;
            As[4*lq+2][r] = a.z; As[4*lq+3][r] = a.w;
            float4 w = *(const float4*)(W + (size_t)(col0 + r) * D + kc + 4 * lq);
            Bs[4*lq+0][r] = w.x; Bs[4*lq+1][r] = w.y;
            Bs[4*lq+2][r] = w.z; Bs[4*lq+3][r] = w.w;
        }
        __syncthreads();
        #pragma unroll
        for (int k = 0; k < 16; k++) {
            float a[8], b[8];
            *(float4*)&a[0] = *(const float4*)&As[k][8 * ty];
            *(float4*)&a[4] = *(const float4*)&As[k][8 * ty + 4];
            *(float4*)&b[0] = *(const float4*)&Bs[k][8 * tx];
            *(float4*)&b[4] = *(const float4*)&Bs[k][8 * tx + 4];
            #pragma unroll
            for (int i = 0; i < 8; i++)
                #pragma unroll
                for (int j = 0; j < 8; j++)
                    acc[i][j] += a[i] * b[j];
        }
        __syncthreads();
    }

    #pragma unroll
    for (int i = 0; i < 8; i++) {
        const int row = row0 + 8 * ty + i;
        #pragma unroll
        for (int j = 0; j < 8; j += 4) {
            const int col = col0 + 8 * tx + j;
            float4 bb = *(const float4*)(bias + col);
            float4 o;
            o.x = acc[i][j+0] + bb.x;
            o.y = acc[i][j+1] + bb.y;
            o.z = acc[i][j+2] + bb.z;
            o.w = acc[i][j+3] + bb.w;
            *(float4*)(Y + (size_t)row * D + col) = o;
        }
    }
}

// ---------------------------------------------------------------------------
// Qt = (Q @ Wk) * scale, written as bf16 hi/lo split. 128x128 tile.
// ---------------------------------------------------------------------------
__global__ __launch_bounds__(256) void proj_nt_split_kernel(
    const float* __restrict__ X, const float* __restrict__ W)
{
    __shared__ float As[16][128];
    __shared__ float Bs[16][128];

    const int tid  = threadIdx.x;
    const int tx   = tid & 15;
    const int ty   = tid >> 4;
    const int row0 = blockIdx.x * 128;
    const int col0 = blockIdx.y * 128;

    float acc[8][8];
    #pragma unroll
    for (int i = 0; i < 8; i++)
        #pragma unroll
        for (int j = 0; j < 8; j++) acc[i][j] = 0.f;

    const int lr = tid >> 2;
    const int lq = tid & 3;

    for (int kc = 0; kc < D; kc += 16) {
        #pragma unroll
        for (int h = 0; h < 2; h++) {
            int r = lr + 64 * h;
            float4 a = *(const float4*)(X + (size_t)(row0 + r) * D + kc + 4 * lq);
            As[4*lq+0][r] = a.x; As[4*lq+1][r] = a.y;
            As[4*lq+2][r] = a.z; As[4*lq+3][r] = a.w;
        }
        #pragma unroll
        for (int h = 0; h < 2; h++) {
            int idx = tid + 256 * h;
            int kk  = idx >> 5;
            int cq  = idx & 31;
            float4 w = *(const float4*)(W + (size_t)(kc + kk) * D + col0 + 4 * cq);
            *(float4*)&Bs[kk][4 * cq] = w;
        }
        __syncthreads();
        #pragma unroll
        for (int k = 0; k < 16; k++) {
            float a[8], b[8];
            *(float4*)&a[0] = *(const float4*)&As[k][8 * ty];
            *(float4*)&a[4] = *(const float4*)&As[k][8 * ty + 4];
            *(float4*)&b[0] = *(const float4*)&Bs[k][8 * tx];
            *(float4*)&b[4] = *(const float4*)&Bs[k][8 * tx + 4];
            #pragma unroll
            for (int i = 0; i < 8; i++)
                #pragma unroll
                for (int j = 0; j < 8; j++)
                    acc[i][j] += a[i] * b[j];
        }
        __syncthreads();
    }

    const float scale = 0.0625f;  // 1/sqrt(256)
    #pragma unroll
    for (int i = 0; i < 8; i++) {
        const size_t row = row0 + 8 * ty + i;
        #pragma unroll
        for (int j = 0; j < 8; j++) {
            const int col = col0 + 8 * tx + j;
            __nv_bfloat16 h, l;
            split_bf16(acc[i][j] * scale, h, l);
            g_Qh[row * D + col] = h;
            g_Ql[row * D + col] = l;
        }
    }
}

// ---------------------------------------------------------------------------
// F_s fp32 -> bf16 hi/lo. 8 elements/thread, vectorized.
// ---------------------------------------------------------------------------
__global__ __launch_bounds__(256) void conv_fs_kernel(const float* __restrict__ Fs)
{
    const size_t i = ((size_t)blockIdx.x * 256 + threadIdx.x) * 8;
    float4 v0 = *(const float4*)(Fs + i);
    float4 v1 = *(const float4*)(Fs + i + 4);
    float x[8] = {v0.x, v0.y, v0.z, v0.w, v1.x, v1.y, v1.z, v1.w};
    __nv_bfloat16 h[8], l[8];
    #pragma unroll
    for (int k = 0; k < 8; k++) split_bf16(x[k], h[k], l[k]);
    uint4 ph, pl;
    ph.x = ((uint32_t)__bfloat16_as_ushort(h[1]) << 16) | __bfloat16_as_ushort(h[0]);
    ph.y = ((uint32_t)__bfloat16_as_ushort(h[3]) << 16) | __bfloat16_as_ushort(h[2]);
    ph.z = ((uint32_t)__bfloat16_as_ushort(h[5]) << 16) | __bfloat16_as_ushort(h[4]);
    ph.w = ((uint32_t)__bfloat16_as_ushort(h[7]) << 16) | __bfloat16_as_ushort(h[6]);
    pl.x = ((uint32_t)__bfloat16_as_ushort(l[1]) << 16) | __bfloat16_as_ushort(l[0]);
    pl.y = ((uint32_t)__bfloat16_as_ushort(l[3]) << 16) | __bfloat16_as_ushort(l[2]);
    pl.z = ((uint32_t)__bfloat16_as_ushort(l[5]) << 16) | __bfloat16_as_ushort(l[4]);
    pl.w = ((uint32_t)__bfloat16_as_ushort(l[7]) << 16) | __bfloat16_as_ushort(l[6]);
    *(uint4*)(g_Fh + i) = ph;
    *(uint4*)(g_Fl + i) = pl;
}

// ---------------------------------------------------------------------------
// cs[t] = (Q[t,:] . bk) * scale. One warp per row.
// ---------------------------------------------------------------------------
__global__ __launch_bounds__(256) void qc_kernel(const float* __restrict__ bk)
{
    const int row  = (blockIdx.x * blockDim.x + threadIdx.x) >> 5;
    const int lane = threadIdx.x & 31;
    if (row >= B * T) return;
    const float* q = g_Q + (size_t)row * D;
    float s = 0.f;
    #pragma unroll
    for (int i = 0; i < 8; i++) s += q[lane + 32 * i] * bk[lane + 32 * i];
    #pragma unroll
    for (int o = 16; o > 0; o >>= 1) s += __shfl_xor_sync(0xffffffffu, s, o);
    if (lane == 0) g_cs[row] = s * 0.0625f;
}

// ---------------------------------------------------------------------------
// mma.sync score kernel with cp.async 2-stage pipeline.
// CTA tile 128(M) x 128(N), K=256 streamed in 8 chunks of 32.
// 8 warps (4 m-tiles x 2 n-halves), warp tile 32x64.
// 3 bf16 terms: Ah*Bh + Al*Bh + Ah*Bl.
// Grid (B, T/128, HW/128) = (32, 2, 32), 256 threads.
// SMEM: 2 stages x {AH,AL,BH,BL} x 8KB = 64KB, + mask.
// Tile layout: 128 rows x 32 cols bf16, 64 B/row, 4 x 16B chunks,
//   off(r,c) = r*64 + ((c ^ ((r>>1)&3)) << 4)   (conflict-free for ldmatrix)
// ---------------------------------------------------------------------------
#define KC       32
#define NCHUNK   (D / KC)          // 8
#define TILE_SZ  8192              // 128*64 bytes
#define STAGE_SZ (4 * TILE_SZ)     // 32768
#define SM_MASK  (2 * STAGE_SZ)    // 65536
#define SM_TOT   (SM_MASK + 512)

// issue cp.async for one 128x32 tile (2 x 16B per thread)
__device__ __forceinline__ void cpa_tile32(uint32_t dst,
                                           const __nv_bfloat16* __restrict__ g,
                                           int kc, int tid)
{
    #pragma unroll
    for (int i = 0; i < 2; i++) {
        const int v = tid + 256 * i;       // 0..511
        const int r = v >> 2;              // 0..127
        const int c = v & 3;               // chunk 0..3
        const uint32_t off = (uint32_t)r * 64u + (uint32_t)((c ^ ((r >> 1) & 3)) << 4);
        CP_ASYNC16(dst + off, g + (size_t)r * D + kc + c * 8);
    }
}

__global__ __launch_bounds__(256, 2)
void score_mma_kernel(const int* __restrict__ Mmask, float* __restrict__ out)
{
    extern __shared__ __align__(128) uint8_t smem[];
    const int b    = blockIdx.x;
    const int t0   = blockIdx.y * 128;
    const int sp   = blockIdx.z;
    const int s0   = sp * 128;
    const int tid  = threadIdx.x;
    const int wid  = tid >> 5;
    const int lane = tid & 31;
    const int wm   = wid & 3;     // m-tile (32 rows)
    const int wn   = wid >> 2;    // n-half (64 cols)
    const uint32_t sb = smem_to_u32(smem);

    const __nv_bfloat16* __restrict__ Ah = g_Qh + (size_t)(b * T + t0) * D;
    const __nv_bfloat16* __restrict__ Al = g_Ql + (size_t)(b * T + t0) * D;
    const __nv_bfloat16* __restrict__ Bh = g_Fh + (size_t)(b * HW + s0) * D;
    const __nv_bfloat16* __restrict__ Bl = g_Fl + (size_t)(b * HW + s0) * D;

    if (tid < 128) ((int*)(smem + SM_MASK))[tid] = Mmask[b * HW + s0 + tid];

    // invariant fragment coords
    const uint32_t rA  = (uint32_t)(wm * 32 + (lane & 15));   // A row, mt=0
    const uint32_t chA = (uint32_t)(lane >> 4);               // A k-sub
    const uint32_t nB  = (uint32_t)(wn * 64 + (lane & 7) + ((lane >> 4) << 3));
    const uint32_t chB = (uint32_t)((lane >> 3) & 1);         // B k-sub

    float acc[2][8][4];
    #pragma unroll
    for (int mt = 0; mt < 2; mt++)
        #pragma unroll
        for (int nt = 0; nt < 8; nt++)
            #pragma unroll
            for (int q = 0; q < 4; q++) acc[mt][nt][q] = 0.f;

    // prologue: stage 0
    {
        const uint32_t st = sb;
        cpa_tile32(st,               Ah, 0, tid);
        cpa_tile32(st + TILE_SZ,     Al, 0, tid);
        cpa_tile32(st + 2 * TILE_SZ, Bh, 0, tid);
        cpa_tile32(st + 3 * TILE_SZ, Bl, 0, tid);
        CP_COMMIT();
    }

    #pragma unroll 1
    for (int j = 0; j < NCHUNK; j++) {
        // issue next stage
        if (j + 1 < NCHUNK) {
            const uint32_t st = sb + ((j + 1) & 1) * STAGE_SZ;
            const int kc = (j + 1) * KC;
            cpa_tile32(st,               Ah, kc, tid);
            cpa_tile32(st + TILE_SZ,     Al, kc, tid);
            cpa_tile32(st + 2 * TILE_SZ, Bh, kc, tid);
            cpa_tile32(st + 3 * TILE_SZ, Bl, kc, tid);
            CP_COMMIT();
            CP_WAIT(1);
        } else {
            CP_WAIT(0);
        }
        __syncthreads();

        const uint32_t st = sb + (j & 1) * STAGE_SZ;

        #pragma unroll
        for (int ks = 0; ks < 2; ks++) {       // two k16 steps per 32-chunk
            uint32_t ah[2][4], al[2][4];
            #pragma unroll
            for (int mt = 0; mt < 2; mt++) {
                const uint32_t r   = rA + (uint32_t)(mt * 16);
                const uint32_t ch  = (uint32_t)(ks * 2) + chA;
                const uint32_t off = r * 64u + (((ch ^ ((r >> 1))) & 3u) << 4);
                ldsm_x4(ah[mt], st + off);
                ldsm_x4(al[mt], st + TILE_SZ + off);
            }
            #pragma unroll
            for (int np = 0; np < 4; np++) {
                const uint32_t n   = nB + (uint32_t)(np * 16);
                const uint32_t ch  = (uint32_t)(ks * 2) + chB;
                const uint32_t off = n * 64u + (((ch ^ ((n >> 1))) & 3u) << 4);
                uint32_t bh[4], bl[4];
                ldsm_x4(bh, st + 2 * TILE_SZ + off);
                ldsm_x4(bl, st + 3 * TILE_SZ + off);
                #pragma unroll
                for (int mt = 0; mt < 2; mt++) {
                    mma_bf16(acc[mt][2*np+0], ah[mt], bh[0], bh[1]);
                    mma_bf16(acc[mt][2*np+1], ah[mt], bh[2], bh[3]);
                    mma_bf16(acc[mt][2*np+0], al[mt], bh[0], bh[1]);
                    mma_bf16(acc[mt][2*np+1], al[mt], bh[2], bh[3]);
                    mma_bf16(acc[mt][2*np+0], ah[mt], bl[0], bl[1]);
                    mma_bf16(acc[mt][2*np+1], ah[mt], bl[2], bl[3]);
                }
            }
        }
        __syncthreads();   // all reads of stage j done before it is refilled at j+2
    }

    // ------------------------------------------------------------------
    // Epilogue: mask, +cs, write logits (float2), per-row max/sumexp
    // ------------------------------------------------------------------
    const float NEGI = neg_inf();
    const int*  msk  = (const int*)(smem + SM_MASK);
    const int   qr   = lane >> 2;
    const int   qc   = (lane & 3) * 2;

    int mk0[8], mk1[8];
    #pragma unroll
    for (int nt = 0; nt < 8; nt++) {
        mk0[nt] = msk[wn * 64 + nt * 8 + qc];
        mk1[nt] = msk[wn * 64 + nt * 8 + qc + 1];
    }

    #pragma unroll
    for (int mt = 0; mt < 2; mt++) {
        #pragma unroll
        for (int inst = 0; inst < 2; inst++) {
            const int r    = wm * 32 + mt * 16 + inst * 8 + qr;
            const int grow = b * T + t0 + r;
            const float cs = g_cs[grow];

            float z[16];
            float rmax = NEGI;
            #pragma unroll
            for (int nt = 0; nt < 8; nt++) {
                const float v0 = acc[mt][nt][inst * 2 + 0] + cs;
                const float v1 = acc[mt][nt][inst * 2 + 1] + cs;
                z[2*nt+0] = (mk0[nt] != 0) ? v0 : NEGI;
                z[2*nt+1] = (mk1[nt] != 0) ? v1 : NEGI;
                rmax = fmaxf(rmax, fmaxf(z[2*nt+0], z[2*nt+1]));
            }
            float* orow = out + (size_t)grow * HW + s0 + wn * 64 + qc;
            #pragma unroll
            for (int nt = 0; nt < 8; nt++)
                *(float2*)(orow + nt * 8) = make_float2(z[2*nt], z[2*nt+1]);

            rmax = fmaxf(rmax, __shfl_xor_sync(0xffffffffu, rmax, 1));
            rmax = fmaxf(rmax, __shfl_xor_sync(0xffffffffu, rmax, 2));

            float rsum = 0.f;
            if (rmax >= FIN_THRESH) {
                #pragma unroll
                for (int j = 0; j < 16; j++) rsum += __expf(z[j] - rmax);
            }
            rsum += __shfl_xor_sync(0xffffffffu, rsum, 1);
            rsum += __shfl_xor_sync(0xffffffffu, rsum, 2);

            if ((lane & 3) == 0) {
                const size_t si = (size_t)grow * SPLIT + sp * 2 + wn;
                g_pm[si] = rmax;
                g_ps[si] = rsum;
            }
        }
    }
}

// ---------------------------------------------------------------------------
// Merge 64 partial stats + normalize in place. Grid: B*T blocks.
// ---------------------------------------------------------------------------
__global__ __launch_bounds__(256) void norm_kernel(float* __restrict__ out)
{
    const int row = blockIdx.x;

    float m = neg_inf();
    for (int i = 0; i < SPLIT; i++) m = fmaxf(m, g_pm[(size_t)row * SPLIT + i]);

    float4* p = reinterpret_cast<float4*>(out + (size_t)row * HW);

    if (m >= FIN_THRESH) {
        float s = 0.f;
        for (int i = 0; i < SPLIT; i++) {
            const float pmv = g_pm[(size_t)row * SPLIT + i];
            const float w   = (pmv >= FIN_THRESH) ? __expf(pmv - m) : 0.f;
            s += g_ps[(size_t)row * SPLIT + i] * w;
        }
        const float rinv = 1.f / s;
        for (int i = threadIdx.x; i < HW / 4; i += 256) {
            float4 v = p[i];
            v.x = __expf(v.x - m) * rinv;
            v.y = __expf(v.y - m) * rinv;
            v.z = __expf(v.z - m) * rinv;
            v.w = __expf(v.w - m) * rinv;
            p[i] = v;
        }
    } else {
        for (int i = threadIdx.x; i < HW / 4; i += 256)
            p[i] = make_float4(0.f, 0.f, 0.f, 0.f);
    }
}

// ---------------------------------------------------------------------------
extern "C" void kernel_launch(void* const* d_in, const int* in_sizes, int n_in,
                              void* d_out, int out_size)
{
    const float* F_a = (const float*)d_in[0];
    const float* F_s = (const float*)d_in[1];
    const int*   M_s = (const int*)  d_in[2];
    const float* Wq  = (const float*)d_in[3];
    const float* bq  = (const float*)d_in[4];
    const float* Wk  = (const float*)d_in[5];
    const float* bk  = (const float*)d_in[6];
    float* out = (float*)d_out;

    static float* qbuf = nullptr;
    if (!qbuf) {
        cudaGetSymbolAddress((void**)&qbuf, g_Q);
        cudaFuncSetAttribute(score_mma_kernel,
                             cudaFuncAttributeMaxDynamicSharedMemorySize, SM_TOT);
    }

    // Q = F_a @ Wq^T + bq
    proj_kernel<<<dim3((B * T) / 128, D / 128), 256>>>(F_a, Wq, bq, qbuf);
    // Qt = (Q @ Wk) * scale -> bf16 hi/lo
    proj_nt_split_kernel<<<dim3((B * T) / 128, D / 128), 256>>>(qbuf, Wk);
    // cs = (Q . bk) * scale
    qc_kernel<<<(B * T * 32) / 256, 256>>>(bk);
    // F_s -> bf16 hi/lo
    conv_fs_kernel<<<(int)(((size_t)B * HW * D) / (256 * 8)), 256>>>(F_s);
    // logits + partial stats (HMMA, cp.async pipelined)
    score_mma_kernel<<<dim3(B, T / 128, HW / 128), 256, SM_TOT>>>(M_s, out);
    // merge + normalize
    norm_kernel<<<B * T, 256>>>(out);
}

// round 13
// speedup vs baseline: 3.9273x; 1.0813x over previous
#include <cuda_runtime.h>
#include <cuda_bf16.h>
#include <cstdint>

#define D      256
#define B      32
#define T      256
#define HW     4096
#define SPLIT  64            // per-row stat chunks (32 s-tiles x 2 n-halves)

// ---------------------------------------------------------------------------
// Device-global scratch (allocations forbidden)
// ---------------------------------------------------------------------------
__device__ float          g_Q [(size_t)B * T * D];     // Q = F_a@Wq^T + bq (fp32)
__device__ __nv_bfloat16  g_Qh[(size_t)B * T * D];     // hi(Qt*scale)
__device__ __nv_bfloat16  g_Ql[(size_t)B * T * D];     // lo(Qt*scale)
__device__ __nv_bfloat16  g_Fh[(size_t)B * HW * D];    // hi(F_s) COMPACT rows
__device__ __nv_bfloat16  g_Fl[(size_t)B * HW * D];    // lo(F_s) COMPACT rows
__device__ float          g_cs[B * T];                 // (Q.bk)*scale
__device__ float          g_pm[(size_t)B * T * SPLIT]; // partial row max
__device__ float          g_ps[(size_t)B * T * SPLIT]; // partial row sumexp
__device__ int            g_idx[B * HW];               // compact -> real col
__device__ int            g_cnt[B];                    // unmasked count / batch

#define FIN_THRESH (-3.0e38f)
__device__ __forceinline__ float neg_inf() { return __int_as_float(0xff800000); }

__device__ __forceinline__ uint32_t smem_to_u32(const void* p) {
    uint32_t a;
    asm("{ .reg .u64 t; cvta.to.shared.u64 t, %1; cvt.u32.u64 %0, t; }"
        : "=r"(a) : "l"(p));
    return a;
}

__device__ __forceinline__ void ldsm_x4(uint32_t* r, uint32_t addr) {
    asm volatile("ldmatrix.sync.aligned.m8n8.x4.shared.b16 {%0,%1,%2,%3}, [%4];"
                 : "=r"(r[0]), "=r"(r[1]), "=r"(r[2]), "=r"(r[3]) : "r"(addr));
}

__device__ __forceinline__ void mma_bf16(float* c, const uint32_t* a,
                                         uint32_t b0, uint32_t b1) {
    asm volatile(
        "mma.sync.aligned.m16n8k16.row.col.f32.bf16.bf16.f32 "
        "{%0,%1,%2,%3}, {%4,%5,%6,%7}, {%8,%9}, {%0,%1,%2,%3};"
        : "+f"(c[0]), "+f"(c[1]), "+f"(c[2]), "+f"(c[3])
        : "r"(a[0]), "r"(a[1]), "r"(a[2]), "r"(a[3]), "r"(b0), "r"(b1));
}

#define CP_ASYNC16(smem, gptr) \
    asm volatile("cp.async.cg.shared.global [%0], [%1], 16;" \
                 :: "r"(smem), "l"(gptr) : "memory")
#define CP_COMMIT() asm volatile("cp.async.commit_group;" ::: "memory")
#define CP_WAIT(n)  asm volatile("cp.async.wait_group %0;" :: "n"(n) : "memory")

__device__ __forceinline__ void split_bf16(float x, __nv_bfloat16& h, __nv_bfloat16& l) {
    h = __float2bfloat16_rn(x);
    l = __float2bfloat16_rn(x - __bfloat162float(h));
}

// ---------------------------------------------------------------------------
// Mask compaction: one block per batch. g_idx[b][j] = j-th unmasked column.
// ---------------------------------------------------------------------------
__global__ __launch_bounds__(256) void compact_kernel(const int* __restrict__ M)
{
    const int b   = blockIdx.x;
    const int tid = threadIdx.x;
    const int lane = tid & 31, wrp = tid >> 5;
    __shared__ int wsum[8];

    const int* mb = M + b * HW;
    const int base = tid * 16;

    int loc[16];
    int cnt = 0;
    #pragma unroll
    for (int i = 0; i < 16; i++) {
        loc[i] = cnt;
        cnt += (mb[base + i] != 0);
    }
    // inclusive warp scan of cnt
    int v = cnt;
    #pragma unroll
    for (int o = 1; o < 32; o <<= 1) {
        int t = __shfl_up_sync(0xffffffffu, v, o);
        if (lane >= o) v += t;
    }
    if (lane == 31) wsum[wrp] = v;
    __syncthreads();
    int woff = 0;
    for (int w = 0; w < wrp; w++) woff += wsum[w];
    const int excl = woff + v - cnt;

    #pragma unroll
    for (int i = 0; i < 16; i++)
        if (mb[base + i] != 0)
            g_idx[b * HW + excl + loc[i]] = base + i;

    if (tid == 255) g_cnt[b] = woff + v;
}

// ---------------------------------------------------------------------------
// Q projection: Y = F_a @ Wq^T + bq  (fp32, 128x128 tile)
// ---------------------------------------------------------------------------
__global__ __launch_bounds__(256) void proj_kernel(
    const float* __restrict__ X, const float* __restrict__ W,
    const float* __restrict__ bias, float* __restrict__ Y)
{
    __shared__ float As[16][128];
    __shared__ float Bs[16][128];

    const int tid  = threadIdx.x;
    const int tx   = tid & 15;
    const int ty   = tid >> 4;
    const int row0 = blockIdx.x * 128;
    const int col0 = blockIdx.y * 128;

    float acc[8][8];
    #pragma unroll
    for (int i = 0; i < 8; i++)
        #pragma unroll
        for (int j = 0; j < 8; j++) acc[i][j] = 0.f;

    const int lr = tid >> 2;
    const int lq = tid & 3;

    for (int kc = 0; kc < D; kc += 16) {
        #pragma unroll
        for (int h = 0; h < 2; h++) {
            int r = lr + 64 * h;
            float4 a = *(const float4*)(X + (size_t)(row0 + r) * D + kc + 4 * lq);
            As[4*lq+0][r] = a.x; As[4*lq+1][r] = a.y;
            As[4*lq+2][r] = a.z; As[4*lq+3][r] = a.w;
            float4 w = *(const float4*)(W + (size_t)(col0 + r) * D + kc + 4 * lq);
            Bs[4*lq+0][r] = w.x; Bs[4*lq+1][r] = w.y;
            Bs[4*lq+2][r] = w.z; Bs[4*lq+3][r] = w.w;
        }
        __syncthreads();
        #pragma unroll
        for (int k = 0; k < 16; k++) {
            float a[8], b[8];
            *(float4*)&a[0] = *(const float4*)&As[k][8 * ty];
            *(float4*)&a[4] = *(const float4*)&As[k][8 * ty + 4];
            *(float4*)&b[0] = *(const float4*)&Bs[k][8 * tx];
            *(float4*)&b[4] = *(const float4*)&Bs[k][8 * tx + 4];
            #pragma unroll
            for (int i = 0; i < 8; i++)
                #pragma unroll
                for (int j = 0; j < 8; j++)
                    acc[i][j] += a[i] * b[j];
        }
        __syncthreads();
    }

    #pragma unroll
    for (int i = 0; i < 8; i++) {
        const int row = row0 + 8 * ty + i;
        #pragma unroll
        for (int j = 0; j < 8; j += 4) {
            const int col = col0 + 8 * tx + j;
            float4 bb = *(const float4*)(bias + col);
            float4 o;
            o.x = acc[i][j+0] + bb.x;
            o.y = acc[i][j+1] + bb.y;
            o.z = acc[i][j+2] + bb.z;
            o.w = acc[i][j+3] + bb.w;
            *(float4*)(Y + (size_t)row * D + col) = o;
        }
    }
}

// ---------------------------------------------------------------------------
// Qt = (Q @ Wk) * scale, written as bf16 hi/lo split. 128x128 tile.
// ---------------------------------------------------------------------------
__global__ __launch_bounds__(256) void proj_nt_split_kernel(
    const float* __restrict__ X, const float* __restrict__ W)
{
    __shared__ float As[16][128];
    __shared__ float Bs[16][128];

    const int tid  = threadIdx.x;
    const int tx   = tid & 15;
    const int ty   = tid >> 4;
    const int row0 = blockIdx.x * 128;
    const int col0 = blockIdx.y * 128;

    float acc[8][8];
    #pragma unroll
    for (int i = 0; i < 8; i++)
        #pragma unroll
        for (int j = 0; j < 8; j++) acc[i][j] = 0.f;

    const int lr = tid >> 2;
    const int lq = tid & 3;

    for (int kc = 0; kc < D; kc += 16) {
        #pragma unroll
        for (int h = 0; h < 2; h++) {
            int r = lr + 64 * h;
            float4 a = *(const float4*)(X + (size_t)(row0 + r) * D + kc + 4 * lq);
            As[4*lq+0][r] = a.x; As[4*lq+1][r] = a.y;
            As[4*lq+2][r] = a.z; As[4*lq+3][r] = a.w;
        }
        #pragma unroll
        for (int h = 0; h < 2; h++) {
            int idx = tid + 256 * h;
            int kk  = idx >> 5;
            int cq  = idx & 31;
            float4 w = *(const float4*)(W + (size_t)(kc + kk) * D + col0 + 4 * cq);
            *(float4*)&Bs[kk][4 * cq] = w;
        }
        __syncthreads();
        #pragma unroll
        for (int k = 0; k < 16; k++) {
            float a[8], b[8];
            *(float4*)&a[0] = *(const float4*)&As[k][8 * ty];
            *(float4*)&a[4] = *(const float4*)&As[k][8 * ty + 4];
            *(float4*)&b[0] = *(const float4*)&Bs[k][8 * tx];
            *(float4*)&b[4] = *(const float4*)&Bs[k][8 * tx + 4];
            #pragma unroll
            for (int i = 0; i < 8; i++)
                #pragma unroll
                for (int j = 0; j < 8; j++)
                    acc[i][j] += a[i] * b[j];
        }
        __syncthreads();
    }

    const float scale = 0.0625f;  // 1/sqrt(256)
    #pragma unroll
    for (int i = 0; i < 8; i++) {
        const size_t row = row0 + 8 * ty + i;
        #pragma unroll
        for (int j = 0; j < 8; j++) {
            const int col = col0 + 8 * tx + j;
            __nv_bfloat16 h, l;
            split_bf16(acc[i][j] * scale, h, l);
            g_Qh[row * D + col] = h;
            g_Ql[row * D + col] = l;
        }
    }
}

// ---------------------------------------------------------------------------
// F_s -> bf16 hi/lo, GATHERED into compact rows. Only unmasked rows converted.
// Grid (B, HW/8). Block: 8 rows x 32 threads, 8 elems each.
// ---------------------------------------------------------------------------
__global__ __launch_bounds__(256) void conv_fs_gather_kernel(const float* __restrict__ Fs)
{
    const int b   = blockIdx.x;
    const int j   = blockIdx.y * 8 + (threadIdx.x >> 5);   // compact row
    if (j >= g_cnt[b]) return;
    const int src = g_idx[b * HW + j];
    const int e   = (threadIdx.x & 31) * 8;

    const float* p = Fs + ((size_t)b * HW + src) * D + e;
    float4 v0 = *(const float4*)(p);
    float4 v1 = *(const float4*)(p + 4);
    float x[8] = {v0.x, v0.y, v0.z, v0.w, v1.x, v1.y, v1.z, v1.w};
    __nv_bfloat16 h[8], l[8];
    #pragma unroll
    for (int k = 0; k < 8; k++) split_bf16(x[k], h[k], l[k]);
    uint4 ph, pl;
    ph.x = ((uint32_t)__bfloat16_as_ushort(h[1]) << 16) | __bfloat16_as_ushort(h[0]);
    ph.y = ((uint32_t)__bfloat16_as_ushort(h[3]) << 16) | __bfloat16_as_ushort(h[2]);
    ph.z = ((uint32_t)__bfloat16_as_ushort(h[5]) << 16) | __bfloat16_as_ushort(h[4]);
    ph.w = ((uint32_t)__bfloat16_as_ushort(h[7]) << 16) | __bfloat16_as_ushort(h[6]);
    pl.x = ((uint32_t)__bfloat16_as_ushort(l[1]) << 16) | __bfloat16_as_ushort(l[0]);
    pl.y = ((uint32_t)__bfloat16_as_ushort(l[3]) << 16) | __bfloat16_as_ushort(l[2]);
    pl.z = ((uint32_t)__bfloat16_as_ushort(l[5]) << 16) | __bfloat16_as_ushort(l[4]);
    pl.w = ((uint32_t)__bfloat16_as_ushort(l[7]) << 16) | __bfloat16_as_ushort(l[6]);
    const size_t o = ((size_t)b * HW + j) * D + e;
    *(uint4*)(g_Fh + o) = ph;
    *(uint4*)(g_Fl + o) = pl;
}

// ---------------------------------------------------------------------------
// cs[t] = (Q[t,:] . bk) * scale. One warp per row.
// ---------------------------------------------------------------------------
__global__ __launch_bounds__(256) void qc_kernel(const float* __restrict__ bk)
{
    const int row  = (blockIdx.x * blockDim.x + threadIdx.x) >> 5;
    const int lane = threadIdx.x & 31;
    if (row >= B * T) return;
    const float* q = g_Q + (size_t)row * D;
    float s = 0.f;
    #pragma unroll
    for (int i = 0; i < 8; i++) s += q[lane + 32 * i] * bk[lane + 32 * i];
    #pragma unroll
    for (int o = 16; o > 0; o >>= 1) s += __shfl_xor_sync(0xffffffffu, s, o);
    if (lane == 0) g_cs[row] = s * 0.0625f;
}

// ---------------------------------------------------------------------------
// mma.sync score kernel over COMPACT columns, cp.async 2-stage pipeline.
// Grid (B, T/128, HW/128); blocks with s0 >= cnt write empty stats and exit.
// Epilogue scatters logits to real columns via g_idx.
// ---------------------------------------------------------------------------
#define KC       32
#define NCHUNK   (D / KC)          // 8
#define TILE_SZ  8192              // 128*64 bytes
#define STAGE_SZ (4 * TILE_SZ)     // 32768
#define SM_IDX   (2 * STAGE_SZ)    // 65536: 128 ints (real col or -1)
#define SM_TOT   (SM_IDX + 512)

__device__ __forceinline__ void cpa_tile32(uint32_t dst,
                                           const __nv_bfloat16* __restrict__ g,
                                           int kc, int tid)
{
    #pragma unroll
    for (int i = 0; i < 2; i++) {
        const int v = tid + 256 * i;       // 0..511
        const int r = v >> 2;              // 0..127
        const int c = v & 3;               // chunk 0..3
        const uint32_t off = (uint32_t)r * 64u + (uint32_t)((c ^ ((r >> 1) & 3)) << 4);
        CP_ASYNC16(dst + off, g + (size_t)r * D + kc + c * 8);
    }
}

__global__ __launch_bounds__(256, 2)
void score_mma_kernel(float* __restrict__ out)
{
    extern __shared__ __align__(128) uint8_t smem[];
    const int b    = blockIdx.x;
    const int t0   = blockIdx.y * 128;
    const int sp   = blockIdx.z;
    const int s0   = sp * 128;
    const int tid  = threadIdx.x;
    const int lane = tid & 31;
    const int wid  = tid >> 5;
    const int wm   = wid & 3;
    const int wn   = wid >> 2;
    const uint32_t sb = smem_to_u32(smem);
    const float NEGI = neg_inf();

    const int cnt = g_cnt[b];
    if (s0 >= cnt) {
        // no live columns in this tile: publish empty partial stats
        for (int i = tid; i < 128; i += 256) {
            const size_t si = (size_t)(b * T + t0 + i) * SPLIT + sp * 2;
            g_pm[si]     = NEGI; g_ps[si]     = 0.f;
            g_pm[si + 1] = NEGI; g_ps[si + 1] = 0.f;
        }
        return;
    }

    const __nv_bfloat16* __restrict__ Ah = g_Qh + (size_t)(b * T + t0) * D;
    const __nv_bfloat16* __restrict__ Al = g_Ql + (size_t)(b * T + t0) * D;
    const __nv_bfloat16* __restrict__ Bh = g_Fh + (size_t)(b * HW + s0) * D;
    const __nv_bfloat16* __restrict__ Bl = g_Fl + (size_t)(b * HW + s0) * D;

    // idx table: real column for each compact column of this tile, -1 if dead
    if (tid < 128)
        ((int*)(smem + SM_IDX))[tid] =
            (s0 + tid < cnt) ? g_idx[b * HW + s0 + tid] : -1;

    const uint32_t rA  = (uint32_t)(wm * 32 + (lane & 15));
    const uint32_t chA = (uint32_t)(lane >> 4);
    const uint32_t nB  = (uint32_t)(wn * 64 + (lane & 7) + ((lane >> 4) << 3));
    const uint32_t chB = (uint32_t)((lane >> 3) & 1);

    float acc[2][8][4];
    #pragma unroll
    for (int mt = 0; mt < 2; mt++)
        #pragma unroll
        for (int nt = 0; nt < 8; nt++)
            #pragma unroll
            for (int q = 0; q < 4; q++) acc[mt][nt][q] = 0.f;

    {
        const uint32_t st = sb;
        cpa_tile32(st,               Ah, 0, tid);
        cpa_tile32(st + TILE_SZ,     Al, 0, tid);
        cpa_tile32(st + 2 * TILE_SZ, Bh, 0, tid);
        cpa_tile32(st + 3 * TILE_SZ, Bl, 0, tid);
        CP_COMMIT();
    }

    #pragma unroll 1
    for (int j = 0; j < NCHUNK; j++) {
        if (j + 1 < NCHUNK) {
            const uint32_t st = sb + ((j + 1) & 1) * STAGE_SZ;
            const int kc = (j + 1) * KC;
            cpa_tile32(st,               Ah, kc, tid);
            cpa_tile32(st + TILE_SZ,     Al, kc, tid);
            cpa_tile32(st + 2 * TILE_SZ, Bh, kc, tid);
            cpa_tile32(st + 3 * TILE_SZ, Bl, kc, tid);
            CP_COMMIT();
            CP_WAIT(1);
        } else {
            CP_WAIT(0);
        }
        __syncthreads();

        const uint32_t st = sb + (j & 1) * STAGE_SZ;

        #pragma unroll
        for (int ks = 0; ks < 2; ks++) {
            uint32_t ah[2][4], al[2][4];
            #pragma unroll
            for (int mt = 0; mt < 2; mt++) {
                const uint32_t r   = rA + (uint32_t)(mt * 16);
                const uint32_t ch  = (uint32_t)(ks * 2) + chA;
                const uint32_t off = r * 64u + (((ch ^ ((r >> 1))) & 3u) << 4);
                ldsm_x4(ah[mt], st + off);
                ldsm_x4(al[mt], st + TILE_SZ + off);
            }
            #pragma unroll
            for (int np = 0; np < 4; np++) {
                const uint32_t n   = nB + (uint32_t)(np * 16);
                const uint32_t ch  = (uint32_t)(ks * 2) + chB;
                const uint32_t off = n * 64u + (((ch ^ ((n >> 1))) & 3u) << 4);
                uint32_t bh[4], bl[4];
                ldsm_x4(bh, st + 2 * TILE_SZ + off);
                ldsm_x4(bl, st + 3 * TILE_SZ + off);
                #pragma unroll
                for (int mt = 0; mt < 2; mt++) {
                    mma_bf16(acc[mt][2*np+0], ah[mt], bh[0], bh[1]);
                    mma_bf16(acc[mt][2*np+1], ah[mt], bh[2], bh[3]);
                    mma_bf16(acc[mt][2*np+0], al[mt], bh[0], bh[1]);
                    mma_bf16(acc[mt][2*np+1], al[mt], bh[2], bh[3]);
                    mma_bf16(acc[mt][2*np+0], ah[mt], bl[0], bl[1]);
                    mma_bf16(acc[mt][2*np+1], ah[mt], bl[2], bl[3]);
                }
            }
        }
        __syncthreads();
    }

    // ------------------------------------------------------------------
    // Epilogue: +cs, stats over live cols, scatter logits to real cols.
    // ------------------------------------------------------------------
    const int* idxs = (const int*)(smem + SM_IDX);
    const int  qr   = lane >> 2;
    const int  qc   = (lane & 3) * 2;

    int rc0[8], rc1[8];   // real columns (-1 = dead)
    #pragma unroll
    for (int nt = 0; nt < 8; nt++) {
        rc0[nt] = idxs[wn * 64 + nt * 8 + qc];
        rc1[nt] = idxs[wn * 64 + nt * 8 + qc + 1];
    }

    #pragma unroll
    for (int mt = 0; mt < 2; mt++) {
        #pragma unroll
        for (int inst = 0; inst < 2; inst++) {
            const int r    = wm * 32 + mt * 16 + inst * 8 + qr;
            const int grow = b * T + t0 + r;
            const float cs = g_cs[grow];

            float z[16];
            float rmax = NEGI;
            #pragma unroll
            for (int nt = 0; nt < 8; nt++) {
                const float v0 = acc[mt][nt][inst * 2 + 0] + cs;
                const float v1 = acc[mt][nt][inst * 2 + 1] + cs;
                z[2*nt+0] = (rc0[nt] >= 0) ? v0 : NEGI;
                z[2*nt+1] = (rc1[nt] >= 0) ? v1 : NEGI;
                rmax = fmaxf(rmax, fmaxf(z[2*nt+0], z[2*nt+1]));
            }
            float* orow = out + (size_t)grow * HW;
            #pragma unroll
            for (int nt = 0; nt < 8; nt++) {
                if (rc0[nt] >= 0) orow[rc0[nt]] = z[2*nt+0];
                if (rc1[nt] >= 0) orow[rc1[nt]] = z[2*nt+1];
            }

            rmax = fmaxf(rmax, __shfl_xor_sync(0xffffffffu, rmax, 1));
            rmax = fmaxf(rmax, __shfl_xor_sync(0xffffffffu, rmax, 2));

            float rsum = 0.f;
            if (rmax >= FIN_THRESH) {
                #pragma unroll
                for (int jj = 0; jj < 16; jj++) rsum += __expf(z[jj] - rmax);
            }
            rsum += __shfl_xor_sync(0xffffffffu, rsum, 1);
            rsum += __shfl_xor_sync(0xffffffffu, rsum, 2);

            if ((lane & 3) == 0) {
                const size_t si = (size_t)grow * SPLIT + sp * 2 + wn;
                g_pm[si] = rmax;
                g_ps[si] = rsum;
            }
        }
    }
}

// ---------------------------------------------------------------------------
// Merge partial stats + normalize; masked columns written as exact 0.
// Grid: B*T blocks.
// ---------------------------------------------------------------------------
__global__ __launch_bounds__(256) void norm_kernel(
    const int* __restrict__ Mmask, float* __restrict__ out)
{
    const int row = blockIdx.x;
    const int b   = row / T;

    float m = neg_inf();
    for (int i = 0; i < SPLIT; i++) m = fmaxf(m, g_pm[(size_t)row * SPLIT + i]);

    float4* p = reinterpret_cast<float4*>(out + (size_t)row * HW);
    const int4* mp = reinterpret_cast<const int4*>(Mmask + b * HW);

    if (m >= FIN_THRESH) {
        float s = 0.f;
        for (int i = 0; i < SPLIT; i++) {
            const float pmv = g_pm[(size_t)row * SPLIT + i];
            const float w   = (pmv >= FIN_THRESH) ? __expf(pmv - m) : 0.f;
            s += g_ps[(size_t)row * SPLIT + i] * w;
        }
        const float rinv = 1.f / s;
        for (int i = threadIdx.x; i < HW / 4; i += 256) {
            float4 v = p[i];
            int4   k = mp[i];
            v.x = (k.x != 0) ? __expf(v.x - m) * rinv : 0.f;
            v.y = (k.y != 0) ? __expf(v.y - m) * rinv : 0.f;
            v.z = (k.z != 0) ? __expf(v.z - m) * rinv : 0.f;
            v.w = (k.w != 0) ? __expf(v.w - m) * rinv : 0.f;
            p[i] = v;
        }
    } else {
        for (int i = threadIdx.x; i < HW / 4; i += 256)
            p[i] = make_float4(0.f, 0.f, 0.f, 0.f);
    }
}

// ---------------------------------------------------------------------------
extern "C" void kernel_launch(void* const* d_in, const int* in_sizes, int n_in,
                              void* d_out, int out_size)
{
    const float* F_a = (const float*)d_in[0];
    const float* F_s = (const float*)d_in[1];
    const int*   M_s = (const int*)  d_in[2];
    const float* Wq  = (const float*)d_in[3];
    const float* bq  = (const float*)d_in[4];
    const float* Wk  = (const float*)d_in[5];
    const float* bk  = (const float*)d_in[6];
    float* out = (float*)d_out;

    static float* qbuf = nullptr;
    if (!qbuf) {
        cudaGetSymbolAddress((void**)&qbuf, g_Q);
        cudaFuncSetAttribute(score_mma_kernel,
                             cudaFuncAttributeMaxDynamicSharedMemorySize, SM_TOT);
    }

    // mask -> compact index list (per batch)
    compact_kernel<<<B, 256>>>(M_s);
    // Q = F_a @ Wq^T + bq
    proj_kernel<<<dim3((B * T) / 128, D / 128), 256>>>(F_a, Wq, bq, qbuf);
    // Qt = (Q @ Wk) * scale -> bf16 hi/lo
    proj_nt_split_kernel<<<dim3((B * T) / 128, D / 128), 256>>>(qbuf, Wk);
    // cs = (Q . bk) * scale
    qc_kernel<<<(B * T * 32) / 256, 256>>>(bk);
    // F_s -> bf16 hi/lo, gathered to compact rows
    conv_fs_gather_kernel<<<dim3(B, HW / 8), 256>>>(F_s);
    // logits over live columns + partial stats
    score_mma_kernel<<<dim3(B, T / 128, HW / 128), 256, SM_TOT>>>(out);
    // merge + normalize + zero-fill masked columns
    norm_kernel<<<B * T, 256>>>(M_s, out);
}

// round 14
// speedup vs baseline: 4.0160x; 1.0226x over previous
#include <cuda_runtime.h>
#include <cuda_bf16.h>
#include <cstdint>

#define D      256
#define B      32
#define T      256
#define HW     4096
#define SPLIT  64            // per-row stat chunks (32 s-tiles x 2 n-halves)

// ---------------------------------------------------------------------------
// Device-global scratch (allocations forbidden)
// ---------------------------------------------------------------------------
__device__ float          g_Q [(size_t)B * T * D];     // Q = F_a@Wq^T + bq (fp32)
__device__ __nv_bfloat16  g_Qh[(size_t)B * T * D];     // hi(Qt*scale)
__device__ __nv_bfloat16  g_Ql[(size_t)B * T * D];     // lo(Qt*scale)
__device__ __nv_bfloat16  g_Fh[(size_t)B * HW * D];    // hi(F_s) COMPACT rows
__device__ __nv_bfloat16  g_Fl[(size_t)B * HW * D];    // lo(F_s) COMPACT rows
__device__ float          g_Sc[(size_t)B * T * HW];    // compact logits (134MB)
__device__ float          g_cs[B * T];                 // (Q.bk)*scale
__device__ float          g_pm[(size_t)B * T * SPLIT]; // partial row max
__device__ float          g_ps[(size_t)B * T * SPLIT]; // partial row sumexp
__device__ int            g_idx[B * HW];               // compact -> real col
__device__ int            g_pos[B * HW];               // real col -> compact pos
__device__ int            g_cnt[B];                    // unmasked count / batch

#define FIN_THRESH (-3.0e38f)
__device__ __forceinline__ float neg_inf() { return __int_as_float(0xff800000); }

__device__ __forceinline__ uint32_t smem_to_u32(const void* p) {
    uint32_t a;
    asm("{ .reg .u64 t; cvta.to.shared.u64 t, %1; cvt.u32.u64 %0, t; }"
        : "=r"(a) : "l"(p));
    return a;
}

__device__ __forceinline__ void ldsm_x4(uint32_t* r, uint32_t addr) {
    asm volatile("ldmatrix.sync.aligned.m8n8.x4.shared.b16 {%0,%1,%2,%3}, [%4];"
                 : "=r"(r[0]), "=r"(r[1]), "=r"(r[2]), "=r"(r[3]) : "r"(addr));
}

__device__ __forceinline__ void mma_bf16(float* c, const uint32_t* a,
                                         uint32_t b0, uint32_t b1) {
    asm volatile(
        "mma.sync.aligned.m16n8k16.row.col.f32.bf16.bf16.f32 "
        "{%0,%1,%2,%3}, {%4,%5,%6,%7}, {%8,%9}, {%0,%1,%2,%3};"
        : "+f"(c[0]), "+f"(c[1]), "+f"(c[2]), "+f"(c[3])
        : "r"(a[0]), "r"(a[1]), "r"(a[2]), "r"(a[3]), "r"(b0), "r"(b1));
}

#define CP_ASYNC16(smem, gptr) \
    asm volatile("cp.async.cg.shared.global [%0], [%1], 16;" \
                 :: "r"(smem), "l"(gptr) : "memory")
#define CP_COMMIT() asm volatile("cp.async.commit_group;" ::: "memory")
#define CP_WAIT(n)  asm volatile("cp.async.wait_group %0;" :: "n"(n) : "memory")

__device__ __forceinline__ void split_bf16(float x, __nv_bfloat16& h, __nv_bfloat16& l) {
    h = __float2bfloat16_rn(x);
    l = __float2bfloat16_rn(x - __bfloat162float(h));
}

// ---------------------------------------------------------------------------
// Mask compaction: one block per batch.
// g_idx[b][j] = j-th unmasked column;  g_pos[b][i] = exclusive live count.
// ---------------------------------------------------------------------------
__global__ __launch_bounds__(256) void compact_kernel(const int* __restrict__ M)
{
    const int b   = blockIdx.x;
    const int tid = threadIdx.x;
    const int lane = tid & 31, wrp = tid >> 5;
    __shared__ int wsum[8];

    const int* mb = M + b * HW;
    const int base = tid * 16;

    int loc[16];
    int cnt = 0;
    #pragma unroll
    for (int i = 0; i < 16; i++) {
        loc[i] = cnt;
        cnt += (mb[base + i] != 0);
    }
    int v = cnt;
    #pragma unroll
    for (int o = 1; o < 32; o <<= 1) {
        int t = __shfl_up_sync(0xffffffffu, v, o);
        if (lane >= o) v += t;
    }
    if (lane == 31) wsum[wrp] = v;
    __syncthreads();
    int woff = 0;
    for (int w = 0; w < wrp; w++) woff += wsum[w];
    const int excl = woff + v - cnt;

    #pragma unroll
    for (int i = 0; i < 16; i++) {
        g_pos[b * HW + base + i] = excl + loc[i];
        if (mb[base + i] != 0)
            g_idx[b * HW + excl + loc[i]] = base + i;
    }

    if (tid == 255) g_cnt[b] = woff + v;
}

// ---------------------------------------------------------------------------
// Q projection: Y = F_a @ Wq^T + bq  (fp32, 128x128 tile)
// ---------------------------------------------------------------------------
__global__ __launch_bounds__(256) void proj_kernel(
    const float* __restrict__ X, const float* __restrict__ W,
    const float* __restrict__ bias, float* __restrict__ Y)
{
    __shared__ float As[16][128];
    __shared__ float Bs[16][128];

    const int tid  = threadIdx.x;
    const int tx   = tid & 15;
    const int ty   = tid >> 4;
    const int row0 = blockIdx.x * 128;
    const int col0 = blockIdx.y * 128;

    float acc[8][8];
    #pragma unroll
    for (int i = 0; i < 8; i++)
        #pragma unroll
        for (int j = 0; j < 8; j++) acc[i][j] = 0.f;

    const int lr = tid >> 2;
    const int lq = tid & 3;

    for (int kc = 0; kc < D; kc += 16) {
        #pragma unroll
        for (int h = 0; h < 2; h++) {
            int r = lr + 64 * h;
            float4 a = *(const float4*)(X + (size_t)(row0 + r) * D + kc + 4 * lq);
            As[4*lq+0][r] = a.x; As[4*lq+1][r] = a.y;
            As[4*lq+2][r] = a.z; As[4*lq+3][r] = a.w;
            float4 w = *(const float4*)(W + (size_t)(col0 + r) * D + kc + 4 * lq);
            Bs[4*lq+0][r] = w.x; Bs[4*lq+1][r] = w.y;
            Bs[4*lq+2][r] = w.z; Bs[4*lq+3][r] = w.w;
        }
        __syncthreads();
        #pragma unroll
        for (int k = 0; k < 16; k++) {
            float a[8], b[8];
            *(float4*)&a[0] = *(const float4*)&As[k][8 * ty];
            *(float4*)&a[4] = *(const float4*)&As[k][8 * ty + 4];
            *(float4*)&b[0] = *(const float4*)&Bs[k][8 * tx];
            *(float4*)&b[4] = *(const float4*)&Bs[k][8 * tx + 4];
            #pragma unroll
            for (int i = 0; i < 8; i++)
                #pragma unroll
                for (int j = 0; j < 8; j++)
                    acc[i][j] += a[i] * b[j];
        }
        __syncthreads();
    }

    #pragma unroll
    for (int i = 0; i < 8; i++) {
        const int row = row0 + 8 * ty + i;
        #pragma unroll
        for (int j = 0; j < 8; j += 4) {
            const int col = col0 + 8 * tx + j;
            float4 bb = *(const float4*)(bias + col);
            float4 o;
            o.x = acc[i][j+0] + bb.x;
            o.y = acc[i][j+1] + bb.y;
            o.z = acc[i][j+2] + bb.z;
            o.w = acc[i][j+3] + bb.w;
            *(float4*)(Y + (size_t)row * D + col) = o;
        }
    }
}

// ---------------------------------------------------------------------------
// Qt = (Q @ Wk) * scale, written as bf16 hi/lo split. 128x128 tile.
// ---------------------------------------------------------------------------
__global__ __launch_bounds__(256) void proj_nt_split_kernel(
    const float* __restrict__ X, const float* __restrict__ W)
{
    __shared__ float As[16][128];
    __shared__ float Bs[16][128];

    const int tid  = threadIdx.x;
    const int tx   = tid & 15;
    const int ty   = tid >> 4;
    const int row0 = blockIdx.x * 128;
    const int col0 = blockIdx.y * 128;

    float acc[8][8];
    #pragma unroll
    for (int i = 0; i < 8; i++)
        #pragma unroll
        for (int j = 0; j < 8; j++) acc[i][j] = 0.f;

    const int lr = tid >> 2;
    const int lq = tid & 3;

    for (int kc = 0; kc < D; kc += 16) {
        #pragma unroll
        for (int h = 0; h < 2; h++) {
            int r = lr + 64 * h;
            float4 a = *(const float4*)(X + (size_t)(row0 + r) * D + kc + 4 * lq);
            As[4*lq+0][r] = a.x; As[4*lq+1][r] = a.y;
            As[4*lq+2][r] = a.z; As[4*lq+3][r] = a.w;
        }
        #pragma unroll
        for (int h = 0; h < 2; h++) {
            int idx = tid + 256 * h;
            int kk  = idx >> 5;
            int cq  = idx & 31;
            float4 w = *(const float4*)(W + (size_t)(kc + kk) * D + col0 + 4 * cq);
            *(float4*)&Bs[kk][4 * cq] = w;
        }
        __syncthreads();
        #pragma unroll
        for (int k = 0; k < 16; k++) {
            float a[8], b[8];
            *(float4*)&a[0] = *(const float4*)&As[k][8 * ty];
            *(float4*)&a[4] = *(const float4*)&As[k][8 * ty + 4];
            *(float4*)&b[0] = *(const float4*)&Bs[k][8 * tx];
            *(float4*)&b[4] = *(const float4*)&Bs[k][8 * tx + 4];
            #pragma unroll
            for (int i = 0; i < 8; i++)
                #pragma unroll
                for (int j = 0; j < 8; j++)
                    acc[i][j] += a[i] * b[j];
        }
        __syncthreads();
    }

    const float scale = 0.0625f;  // 1/sqrt(256)
    #pragma unroll
    for (int i = 0; i < 8; i++) {
        const size_t row = row0 + 8 * ty + i;
        #pragma unroll
        for (int j = 0; j < 8; j++) {
            const int col = col0 + 8 * tx + j;
            __nv_bfloat16 h, l;
            split_bf16(acc[i][j] * scale, h, l);
            g_Qh[row * D + col] = h;
            g_Ql[row * D + col] = l;
        }
    }
}

// ---------------------------------------------------------------------------
// F_s -> bf16 hi/lo, GATHERED into compact rows.
// Grid (B, HW/8). Block: 8 rows x 32 threads, 8 elems each.
// ---------------------------------------------------------------------------
__global__ __launch_bounds__(256) void conv_fs_gather_kernel(const float* __restrict__ Fs)
{
    const int b   = blockIdx.x;
    const int j   = blockIdx.y * 8 + (threadIdx.x >> 5);   // compact row
    if (j >= g_cnt[b]) return;
    const int src = g_idx[b * HW + j];
    const int e   = (threadIdx.x & 31) * 8;

    const float* p = Fs + ((size_t)b * HW + src) * D + e;
    float4 v0 = *(const float4*)(p);
    float4 v1 = *(const float4*)(p + 4);
    float x[8] = {v0.x, v0.y, v0.z, v0.w, v1.x, v1.y, v1.z, v1.w};
    __nv_bfloat16 h[8], l[8];
    #pragma unroll
    for (int k = 0; k < 8; k++) split_bf16(x[k], h[k], l[k]);
    uint4 ph, pl;
    ph.x = ((uint32_t)__bfloat16_as_ushort(h[1]) << 16) | __bfloat16_as_ushort(h[0]);
    ph.y = ((uint32_t)__bfloat16_as_ushort(h[3]) << 16) | __bfloat16_as_ushort(h[2]);
    ph.z = ((uint32_t)__bfloat16_as_ushort(h[5]) << 16) | __bfloat16_as_ushort(h[4]);
    ph.w = ((uint32_t)__bfloat16_as_ushort(h[7]) << 16) | __bfloat16_as_ushort(h[6]);
    pl.x = ((uint32_t)__bfloat16_as_ushort(l[1]) << 16) | __bfloat16_as_ushort(l[0]);
    pl.y = ((uint32_t)__bfloat16_as_ushort(l[3]) << 16) | __bfloat16_as_ushort(l[2]);
    pl.z = ((uint32_t)__bfloat16_as_ushort(l[5]) << 16) | __bfloat16_as_ushort(l[4]);
    pl.w = ((uint32_t)__bfloat16_as_ushort(l[7]) << 16) | __bfloat16_as_ushort(l[6]);
    const size_t o = ((size_t)b * HW + j) * D + e;
    *(uint4*)(g_Fh + o) = ph;
    *(uint4*)(g_Fl + o) = pl;
}

// ---------------------------------------------------------------------------
// cs[t] = (Q[t,:] . bk) * scale. One warp per row.
// ---------------------------------------------------------------------------
__global__ __launch_bounds__(256) void qc_kernel(const float* __restrict__ bk)
{
    const int row  = (blockIdx.x * blockDim.x + threadIdx.x) >> 5;
    const int lane = threadIdx.x & 31;
    if (row >= B * T) return;
    const float* q = g_Q + (size_t)row * D;
    float s = 0.f;
    #pragma unroll
    for (int i = 0; i < 8; i++) s += q[lane + 32 * i] * bk[lane + 32 * i];
    #pragma unroll
    for (int o = 16; o > 0; o >>= 1) s += __shfl_xor_sync(0xffffffffu, s, o);
    if (lane == 0) g_cs[row] = s * 0.0625f;
}

// ---------------------------------------------------------------------------
// mma.sync score kernel over COMPACT columns, cp.async pipeline.
// Writes logits COALESCED to compact scratch g_Sc via smem staging.
// ---------------------------------------------------------------------------
#define KC       32
#define NCHUNK   (D / KC)          // 8
#define TILE_SZ  8192              // 128*64 bytes
#define STAGE_SZ (4 * TILE_SZ)     // 32768
#define SM_IDX   (2 * STAGE_SZ)    // 65536: 128 ints
#define SM_TOT   66048             // = 128*129*4 staging (overlaps everything)

__device__ __forceinline__ void cpa_tile32(uint32_t dst,
                                           const __nv_bfloat16* __restrict__ g,
                                           int kc, int tid)
{
    #pragma unroll
    for (int i = 0; i < 2; i++) {
        const int v = tid + 256 * i;       // 0..511
        const int r = v >> 2;              // 0..127
        const int c = v & 3;               // chunk 0..3
        const uint32_t off = (uint32_t)r * 64u + (uint32_t)((c ^ ((r >> 1) & 3)) << 4);
        CP_ASYNC16(dst + off, g + (size_t)r * D + kc + c * 8);
    }
}

__global__ __launch_bounds__(256, 2)
void score_mma_kernel()
{
    extern __shared__ __align__(128) uint8_t smem[];
    const int b    = blockIdx.x;
    const int t0   = blockIdx.y * 128;
    const int sp   = blockIdx.z;
    const int s0   = sp * 128;
    const int tid  = threadIdx.x;
    const int lane = tid & 31;
    const int wid  = tid >> 5;
    const int wm   = wid & 3;
    const int wn   = wid >> 2;
    const uint32_t sb = smem_to_u32(smem);
    const float NEGI = neg_inf();

    const int cnt = g_cnt[b];
    if (s0 >= cnt) {
        for (int i = tid; i < 128; i += 256) {
            const size_t si = (size_t)(b * T + t0 + i) * SPLIT + sp * 2;
            g_pm[si]     = NEGI; g_ps[si]     = 0.f;
            g_pm[si + 1] = NEGI; g_ps[si + 1] = 0.f;
        }
        return;
    }

    const __nv_bfloat16* __restrict__ Ah = g_Qh + (size_t)(b * T + t0) * D;
    const __nv_bfloat16* __restrict__ Al = g_Ql + (size_t)(b * T + t0) * D;
    const __nv_bfloat16* __restrict__ Bh = g_Fh + (size_t)(b * HW + s0) * D;
    const __nv_bfloat16* __restrict__ Bl = g_Fl + (size_t)(b * HW + s0) * D;

    // live-flag table for this tile's 128 compact columns
    if (tid < 128)
        ((int*)(smem + SM_IDX))[tid] = (s0 + tid < cnt) ? 1 : 0;

    const uint32_t rA  = (uint32_t)(wm * 32 + (lane & 15));
    const uint32_t chA = (uint32_t)(lane >> 4);
    const uint32_t nB  = (uint32_t)(wn * 64 + (lane & 7) + ((lane >> 4) << 3));
    const uint32_t chB = (uint32_t)((lane >> 3) & 1);

    float acc[2][8][4];
    #pragma unroll
    for (int mt = 0; mt < 2; mt++)
        #pragma unroll
        for (int nt = 0; nt < 8; nt++)
            #pragma unroll
            for (int q = 0; q < 4; q++) acc[mt][nt][q] = 0.f;

    {
        const uint32_t st = sb;
        cpa_tile32(st,               Ah, 0, tid);
        cpa_tile32(st + TILE_SZ,     Al, 0, tid);
        cpa_tile32(st + 2 * TILE_SZ, Bh, 0, tid);
        cpa_tile32(st + 3 * TILE_SZ, Bl, 0, tid);
        CP_COMMIT();
    }

    #pragma unroll 1
    for (int j = 0; j < NCHUNK; j++) {
        if (j + 1 < NCHUNK) {
            const uint32_t st = sb + ((j + 1) & 1) * STAGE_SZ;
            const int kc = (j + 1) * KC;
            cpa_tile32(st,               Ah, kc, tid);
            cpa_tile32(st + TILE_SZ,     Al, kc, tid);
            cpa_tile32(st + 2 * TILE_SZ, Bh, kc, tid);
            cpa_tile32(st + 3 * TILE_SZ, Bl, kc, tid);
            CP_COMMIT();
            CP_WAIT(1);
        } else {
            CP_WAIT(0);
        }
        __syncthreads();

        const uint32_t st = sb + (j & 1) * STAGE_SZ;

        #pragma unroll
        for (int ks = 0; ks < 2; ks++) {
            uint32_t ah[2][4], al[2][4];
            #pragma unroll
            for (int mt = 0; mt < 2; mt++) {
                const uint32_t r   = rA + (uint32_t)(mt * 16);
                const uint32_t ch  = (uint32_t)(ks * 2) + chA;
                const uint32_t off = r * 64u + (((ch ^ ((r >> 1))) & 3u) << 4);
                ldsm_x4(ah[mt], st + off);
                ldsm_x4(al[mt], st + TILE_SZ + off);
            }
            #pragma unroll
            for (int np = 0; np < 4; np++) {
                const uint32_t n   = nB + (uint32_t)(np * 16);
                const uint32_t ch  = (uint32_t)(ks * 2) + chB;
                const uint32_t off = n * 64u + (((ch ^ ((n >> 1))) & 3u) << 4);
                uint32_t bh[4], bl[4];
                ldsm_x4(bh, st + 2 * TILE_SZ + off);
                ldsm_x4(bl, st + 3 * TILE_SZ + off);
                #pragma unroll
                for (int mt = 0; mt < 2; mt++) {
                    mma_bf16(acc[mt][2*np+0], ah[mt], bh[0], bh[1]);
                    mma_bf16(acc[mt][2*np+1], ah[mt], bh[2], bh[3]);
                    mma_bf16(acc[mt][2*np+0], al[mt], bh[0], bh[1]);
                    mma_bf16(acc[mt][2*np+1], al[mt], bh[2], bh[3]);
                    mma_bf16(acc[mt][2*np+0], ah[mt], bl[0], bl[1]);
                    mma_bf16(acc[mt][2*np+1], ah[mt], bl[2], bl[3]);
                }
            }
        }
        __syncthreads();
    }

    // ------------------------------------------------------------------
    // Epilogue: +cs, stats over live cols, stage to smem, coalesced store
    // to compact scratch g_Sc. Staging (128x129 fp32) reuses ALL smem.
    // ------------------------------------------------------------------
    const int* lv = (const int*)(smem + SM_IDX);
    const int  qr = lane >> 2;
    const int  qc = (lane & 3) * 2;

    int lv0[8], lv1[8];
    #pragma unroll
    for (int nt = 0; nt < 8; nt++) {
        lv0[nt] = lv[wn * 64 + nt * 8 + qc];
        lv1[nt] = lv[wn * 64 + nt * 8 + qc + 1];
    }
    __syncthreads();   // everyone has read lv before staging overwrites it

    float* Sz = (float*)smem;   // stride 129

    #pragma unroll
    for (int mt = 0; mt < 2; mt++) {
        #pragma unroll
        for (int inst = 0; inst < 2; inst++) {
            const int r    = wm * 32 + mt * 16 + inst * 8 + qr;
            const int grow = b * T + t0 + r;
            const float cs = g_cs[grow];

            float z[16];
            float rmax = NEGI;
            #pragma unroll
            for (int nt = 0; nt < 8; nt++) {
                const float v0 = acc[mt][nt][inst * 2 + 0] + cs;
                const float v1 = acc[mt][nt][inst * 2 + 1] + cs;
                z[2*nt+0] = lv0[nt] ? v0 : NEGI;
                z[2*nt+1] = lv1[nt] ? v1 : NEGI;
                rmax = fmaxf(rmax, fmaxf(z[2*nt+0], z[2*nt+1]));
            }
            #pragma unroll
            for (int nt = 0; nt < 8; nt++) {
                Sz[r * 129 + wn * 64 + nt * 8 + qc]     = z[2*nt+0];
                Sz[r * 129 + wn * 64 + nt * 8 + qc + 1] = z[2*nt+1];
            }

            rmax = fmaxf(rmax, __shfl_xor_sync(0xffffffffu, rmax, 1));
            rmax = fmaxf(rmax, __shfl_xor_sync(0xffffffffu, rmax, 2));

            float rsum = 0.f;
            if (rmax >= FIN_THRESH) {
                #pragma unroll
                for (int jj = 0; jj < 16; jj++) rsum += __expf(z[jj] - rmax);
            }
            rsum += __shfl_xor_sync(0xffffffffu, rsum, 1);
            rsum += __shfl_xor_sync(0xffffffffu, rsum, 2);

            if ((lane & 3) == 0) {
                const size_t si = (size_t)grow * SPLIT + sp * 2 + wn;
                g_pm[si] = rmax;
                g_ps[si] = rsum;
            }
        }
    }
    __syncthreads();

    // coalesced copy-out: 256 threads, 128 rows x 128 floats
    {
        const int row = tid >> 1;
        const int sg  = tid & 1;
        const float* src = Sz + row * 129 + sg * 64;
        float* dst = g_Sc + (size_t)(b * T + t0 + row) * HW + s0 + sg * 64;
        #pragma unroll
        for (int q = 0; q < 16; q++) {
            *(float4*)(dst + 4 * q) =
                make_float4(src[4*q], src[4*q+1], src[4*q+2], src[4*q+3]);
        }
    }
}

// ---------------------------------------------------------------------------
// Merge partial stats + normalize from COMPACT logits; masked cols -> 0.
// out[i] = mask[i] ? exp(Sc[pos[i]] - m) / s : 0.  Fully coalesced writes.
// Grid: B*T blocks.
// ---------------------------------------------------------------------------
__global__ __launch_bounds__(256) void norm_kernel(
    const int* __restrict__ Mmask, float* __restrict__ out)
{
    const int row = blockIdx.x;
    const int b   = row / T;

    float m = neg_inf();
    for (int i = 0; i < SPLIT; i++) m = fmaxf(m, g_pm[(size_t)row * SPLIT + i]);

    float4* p = reinterpret_cast<float4*>(out + (size_t)row * HW);
    const int4* mp = reinterpret_cast<const int4*>(Mmask + b * HW);
    const int4* pp = reinterpret_cast<const int4*>(g_pos + b * HW);
    const float* C = g_Sc + (size_t)row * HW;

    if (m >= FIN_THRESH) {
        float s = 0.f;
        for (int i = 0; i < SPLIT; i++) {
            const float pmv = g_pm[(size_t)row * SPLIT + i];
            const float w   = (pmv >= FIN_THRESH) ? __expf(pmv - m) : 0.f;
            s += g_ps[(size_t)row * SPLIT + i] * w;
        }
        const float rinv = 1.f / s;
        for (int i = threadIdx.x; i < HW / 4; i += 256) {
            const int4 k  = mp[i];
            const int4 ps = pp[i];
            float4 v;
            v.x = (k.x != 0) ? __expf(C[ps.x] - m) * rinv : 0.f;
            v.y = (k.y != 0) ? __expf(C[ps.y] - m) * rinv : 0.f;
            v.z = (k.z != 0) ? __expf(C[ps.z] - m) * rinv : 0.f;
            v.w = (k.w != 0) ? __expf(C[ps.w] - m) * rinv : 0.f;
            p[i] = v;
        }
    } else {
        for (int i = threadIdx.x; i < HW / 4; i += 256)
            p[i] = make_float4(0.f, 0.f, 0.f, 0.f);
    }
}

// ---------------------------------------------------------------------------
extern "C" void kernel_launch(void* const* d_in, const int* in_sizes, int n_in,
                              void* d_out, int out_size)
{
    const float* F_a = (const float*)d_in[0];
    const float* F_s = (const float*)d_in[1];
    const int*   M_s = (const int*)  d_in[2];
    const float* Wq  = (const float*)d_in[3];
    const float* bq  = (const float*)d_in[4];
    const float* Wk  = (const float*)d_in[5];
    const float* bk  = (const float*)d_in[6];
    float* out = (float*)d_out;

    static float* qbuf = nullptr;
    if (!qbuf) {
        cudaGetSymbolAddress((void**)&qbuf, g_Q);
        cudaFuncSetAttribute(score_mma_kernel,
                             cudaFuncAttributeMaxDynamicSharedMemorySize, SM_TOT);
    }

    compact_kernel<<<B, 256>>>(M_s);
    proj_kernel<<<dim3((B * T) / 128, D / 128), 256>>>(F_a, Wq, bq, qbuf);
    proj_nt_split_kernel<<<dim3((B * T) / 128, D / 128), 256>>>(qbuf, Wk);
    qc_kernel<<<(B * T * 32) / 256, 256>>>(bk);
    conv_fs_gather_kernel<<<dim3(B, HW / 8), 256>>>(F_s);
    score_mma_kernel<<<dim3(B, T / 128, HW / 128), 256, SM_TOT>>>();
    norm_kernel<<<B * T, 256>>>(M_s, out);
}